// round 11
// baseline (speedup 1.0000x reference)
#include <cuda_runtime.h>
#include <cuda_bf16.h>
#include <math.h>
#include <stdint.h>

#define B_    512
#define S_    128
#define H_    768
#define DS_   384
#define NL_   40
#define H3_   2304
#define NP2_  448          // packed N padded to 7*64
#define TEMP_INV_ 20.0f
#define ALPHA_    0.15f
#define GAMMA_    7.5f
#define EPS_      1e-8f

// ---------------- scratch ----------------
__device__ __nv_bfloat16 g_RHb[B_ * H3_];        // tanh(concat) bf16  512x2304
__device__ __nv_bfloat16 g_TOKSb[B_ * 4 * H_];   // bf16 2048x768
__device__ __nv_bfloat16 g_Wd[H_ * H_];          // dense_w^T bf16 [N=768, K=768]
__device__ __nv_bfloat16 g_Wp[NP2_ * H3_];       // packed W^T bf16 [N=448, K=2304]
__device__ __nv_bfloat16 g_rdescb[B_ * DS_];     // rdesc bf16
__device__ __nv_bfloat16 g_relb[B_ * DS_];       // rel bf16
__device__ __nv_bfloat16 g_Db[B_ * 4 * H_];      // tanh dense out bf16 2048x768
__device__ float g_biasP[NP2_];
__device__ float g_P1[6 * B_ * NP2_];            // packed partials
__device__ float g_P2[6 * B_ * B_];              // C partials
__device__ float g_P3[6 * B_ * B_];              // cos partials
__device__ float g_norms[4 * B_];                // recip norms: rel, rdesc, z1, z2
__device__ float g_ce[B_];
__device__ float g_m[B_];
__device__ float g_cl[B_];

__device__ __forceinline__ uint32_t smem_u32(const void* p) {
    uint32_t a;
    asm("{ .reg .u64 t; cvta.to.shared.u64 t, %1; cvt.u32.u64 %0, t; }" : "=r"(a) : "l"(p));
    return a;
}

// ================= mma.sync bf16 NT GEMM, 4-stage cp.async pipeline =================
// D tile 128x64 = A[M,K](bf16 rm, lda) @ B[N,K]^T (bf16 rm, ldb)
// K from kBeg=z*kChunk, kChunk % 64 == 0. 8 warps 4(M)x2(N), warp tile 32x32.
// MODE 0: raw fp32 -> C + z*M*ldc ; MODE 1: tanh(acc+bias) -> Obf bf16 only
#define KT_ 64
#define SPAD_ 72
#define STAGE_ELEMS_ ((128 + 64) * SPAD_)
#define NSTAGE_ 4
#define DYN_SMEM_BYTES_ (NSTAGE_ * STAGE_ELEMS_ * 2)

template<int MODE>
__global__ __launch_bounds__(256, 1)
void mma_nt(const __nv_bfloat16* __restrict__ A, const __nv_bfloat16* __restrict__ B,
            float* __restrict__ C, const float* __restrict__ bias,
            __nv_bfloat16* __restrict__ Obf,
            int M, int N, int K, int lda, int ldb, int ldc, int kChunk)
{
    extern __shared__ __nv_bfloat16 dyn[];

    const int tid  = threadIdx.x;
    const int warp = tid >> 5, lane = tid & 31;
    const int wm = warp >> 1, wn = warp & 1;
    const int bm = blockIdx.y * 128, bn = blockIdx.x * 64;
    const int kBeg = blockIdx.z * kChunk;

    const int arow = tid >> 1, ac0 = (tid & 1) * 32;   // A: 4 x 16B per thread
    const __nv_bfloat16* Ag = A + (size_t)(bm + arow) * lda + ac0;
    const int brow = tid >> 2, bc0 = (tid & 3) * 16;   // B: 2 x 16B per thread
    const __nv_bfloat16* Bg = B + (size_t)(bn + brow) * ldb + bc0;

    const int alr = lane & 15, alc = (lane >> 4) << 3;
    const int blr = lane & 7,  blc = ((lane >> 3) & 1) << 3;

    float acc[2][4][4];
#pragma unroll
    for (int mi = 0; mi < 2; mi++)
#pragma unroll
        for (int ni = 0; ni < 4; ni++)
#pragma unroll
            for (int r = 0; r < 4; r++) acc[mi][ni][r] = 0.f;

    const int nTiles = kChunk / KT_;

    auto stage = [&](int t) {
        __nv_bfloat16* buf = dyn + (t % NSTAGE_) * STAGE_ELEMS_;
        const int k0 = kBeg + t * KT_;
        uint32_t sa = smem_u32(buf + arow * SPAD_ + ac0);
        const __nv_bfloat16* ag = Ag + k0;
#pragma unroll
        for (int j = 0; j < 4; j++)
            asm volatile("cp.async.cg.shared.global [%0], [%1], 16;"
                         :: "r"(sa + j * 16), "l"(ag + j * 8) : "memory");
        uint32_t sb = smem_u32(buf + 128 * SPAD_ + brow * SPAD_ + bc0);
        const __nv_bfloat16* bg = Bg + k0;
#pragma unroll
        for (int j = 0; j < 2; j++)
            asm volatile("cp.async.cg.shared.global [%0], [%1], 16;"
                         :: "r"(sb + j * 16), "l"(bg + j * 8) : "memory");
        asm volatile("cp.async.commit_group;" ::: "memory");
    };

    for (int t = 0; t < NSTAGE_ - 1 && t < nTiles; t++) stage(t);

    for (int t = 0; t < nTiles; t++) {
        // allowed pending = min(2, nTiles-1-t): groups <= t are then complete
        const int rem = nTiles - 1 - t;
        if (rem == 0)      asm volatile("cp.async.wait_group 0;" ::: "memory");
        else if (rem == 1) asm volatile("cp.async.wait_group 1;" ::: "memory");
        else               asm volatile("cp.async.wait_group 2;" ::: "memory");
        __syncthreads();
        if (t + NSTAGE_ - 1 < nTiles) stage(t + NSTAGE_ - 1);

        const __nv_bfloat16* cA = dyn + (t % NSTAGE_) * STAGE_ELEMS_;
        const __nv_bfloat16* cB = cA + 128 * SPAD_;
#pragma unroll
        for (int ks = 0; ks < KT_ / 16; ks++) {
            const int kk = ks * 16;
            uint32_t a[2][4], b[4][2];
#pragma unroll
            for (int mi = 0; mi < 2; mi++) {
                uint32_t addr = smem_u32(cA + (wm * 32 + mi * 16 + alr) * SPAD_ + kk + alc);
                asm volatile("ldmatrix.sync.aligned.m8n8.x4.shared.b16 {%0,%1,%2,%3}, [%4];"
                             : "=r"(a[mi][0]), "=r"(a[mi][1]), "=r"(a[mi][2]), "=r"(a[mi][3])
                             : "r"(addr));
            }
#pragma unroll
            for (int ni = 0; ni < 4; ni++) {
                uint32_t addr = smem_u32(cB + (wn * 32 + ni * 8 + blr) * SPAD_ + kk + blc);
                asm volatile("ldmatrix.sync.aligned.m8n8.x2.shared.b16 {%0,%1}, [%2];"
                             : "=r"(b[ni][0]), "=r"(b[ni][1]) : "r"(addr));
            }
#pragma unroll
            for (int mi = 0; mi < 2; mi++)
#pragma unroll
                for (int ni = 0; ni < 4; ni++) {
                    asm volatile(
                        "mma.sync.aligned.m16n8k16.row.col.f32.bf16.bf16.f32 "
                        "{%0,%1,%2,%3}, {%4,%5,%6,%7}, {%8,%9}, {%0,%1,%2,%3};"
                        : "+f"(acc[mi][ni][0]), "+f"(acc[mi][ni][1]),
                          "+f"(acc[mi][ni][2]), "+f"(acc[mi][ni][3])
                        : "r"(a[mi][0]), "r"(a[mi][1]), "r"(a[mi][2]), "r"(a[mi][3]),
                          "r"(b[ni][0]), "r"(b[ni][1]));
                }
        }
        if (t + 1 < nTiles) __syncthreads();   // protect buffer being re-staged next iter
    }

    const int g = lane >> 2, cpair = (lane & 3) * 2;
#pragma unroll
    for (int mi = 0; mi < 2; mi++) {
#pragma unroll
        for (int half = 0; half < 2; half++) {
            const int row = bm + wm * 32 + mi * 16 + g + half * 8;
#pragma unroll
            for (int ni = 0; ni < 4; ni++) {
                const int col = bn + wn * 32 + ni * 8 + cpair;
                float v0 = acc[mi][ni][half * 2 + 0];
                float v1 = acc[mi][ni][half * 2 + 1];
                if (MODE == 0) {
                    float* Co = C + (size_t)blockIdx.z * M * ldc + (size_t)row * ldc + col;
                    Co[0] = v0; Co[1] = v1;
                } else {
                    float t0 = tanhf(v0 + bias[col]);
                    float t1 = tanhf(v1 + bias[col + 1]);
                    *(__nv_bfloat162*)(Obf + (size_t)row * ldc + col) =
                        __floats2bfloat162_rn(t0, t1);
                }
            }
        }
    }
}

// ---------------- gather + tanh -> bf16 ----------------
__global__ void gather_kernel(const float* __restrict__ bert,
                              const int* __restrict__ eidx,
                              __nv_bfloat16* __restrict__ RHb,
                              __nv_bfloat16* __restrict__ TOKSb)
{
    int b = blockIdx.x, t = threadIdx.x;  // 0..191
    const float* base0 = bert + (size_t)b * 2 * S_ * H_;
    const float* base1 = base0 + S_ * H_;
    int i0 = eidx[b*4+0], i1 = eidx[b*4+1], i2 = eidx[b*4+2], i3 = eidx[b*4+3];
    float4 c  = ((const float4*)base0)[t];
    float4 hh = ((const float4*)(base0 + (size_t)i0*H_))[t];
    float4 tl = ((const float4*)(base0 + (size_t)i1*H_))[t];
    float4 a2 = ((const float4*)(base1 + (size_t)i2*H_))[t];
    float4 b2 = ((const float4*)(base1 + (size_t)i3*H_))[t];

    __nv_bfloat162* rh = (__nv_bfloat162*)(RHb + (size_t)b * H3_);
    __nv_bfloat162* tk = (__nv_bfloat162*)(TOKSb + (size_t)b * 4 * H_);
    rh[2*t]       = __floats2bfloat162_rn(tanhf(c.x),  tanhf(c.y));
    rh[2*t+1]     = __floats2bfloat162_rn(tanhf(c.z),  tanhf(c.w));
    rh[384+2*t]   = __floats2bfloat162_rn(tanhf(hh.x), tanhf(hh.y));
    rh[384+2*t+1] = __floats2bfloat162_rn(tanhf(hh.z), tanhf(hh.w));
    rh[768+2*t]   = __floats2bfloat162_rn(tanhf(tl.x), tanhf(tl.y));
    rh[768+2*t+1] = __floats2bfloat162_rn(tanhf(tl.z), tanhf(tl.w));
    tk[2*t]        = __floats2bfloat162_rn(hh.x, hh.y);
    tk[2*t+1]      = __floats2bfloat162_rn(hh.z, hh.w);
    tk[384+2*t]    = __floats2bfloat162_rn(tl.x, tl.y);
    tk[384+2*t+1]  = __floats2bfloat162_rn(tl.z, tl.w);
    tk[768+2*t]    = __floats2bfloat162_rn(a2.x, a2.y);
    tk[768+2*t+1]  = __floats2bfloat162_rn(a2.z, a2.w);
    tk[1152+2*t]   = __floats2bfloat162_rn(b2.x, b2.y);
    tk[1152+2*t+1] = __floats2bfloat162_rn(b2.z, b2.w);
}

// ---------------- build transposed bf16 weights ----------------
__global__ void pack_kernel(const float* __restrict__ dense_w,
                            const float* __restrict__ cls_w, const float* __restrict__ fc_w,
                            const float* __restrict__ cls_b, const float* __restrict__ fc_b,
                            const float* __restrict__ rdesc,
                            __nv_bfloat16* __restrict__ Wd, __nv_bfloat16* __restrict__ Wp,
                            __nv_bfloat16* __restrict__ rdescb, float* __restrict__ biasP)
{
    int idx = blockIdx.x * blockDim.x + threadIdx.x;
    int stride = gridDim.x * blockDim.x;
    for (int i = idx; i < H_ * H_; i += stride) {
        int n = i / H_, k = i % H_;
        Wd[i] = __float2bfloat16_rn(dense_w[(size_t)k * H_ + n]);
    }
    for (int i = idx; i < NP2_ * H3_; i += stride) {
        int n = i / H3_, k = i % H3_;
        float v = 0.f;
        if (n < NL_)            v = cls_w[(size_t)k * NL_ + n];
        else if (n < NL_ + DS_) v = fc_w[(size_t)k * DS_ + (n - NL_)];
        Wp[i] = __float2bfloat16_rn(v);
    }
    for (int i = idx; i < B_ * DS_; i += stride)
        rdescb[i] = __float2bfloat16_rn(rdesc[i]);
    if (idx < NP2_)
        biasP[idx] = (idx < NL_) ? cls_b[idx] : ((idx < NL_ + DS_) ? fc_b[idx - NL_] : 0.f);
}

// ---------------- fused post-GEMM: reduce P1 + bias + CE + all norms ----------------
__global__ void post_kernel(const float* __restrict__ P1, const float* __restrict__ biasP,
                            const float* __restrict__ rdesc, const __nv_bfloat16* __restrict__ Db,
                            const int* __restrict__ lab,
                            __nv_bfloat16* __restrict__ relb,
                            float* __restrict__ norms, float* __restrict__ ce)
{
    const int b = blockIdx.x, which = blockIdx.y, tid = threadIdx.x;
    __shared__ float red[256];
    __shared__ float vals[NP2_];

    if (which == 0) {
        const int total = B_ * NP2_;
        for (int c = tid; c < NP2_; c += 256) {
            float s = biasP[c];
            int idx = b * NP2_ + c;
#pragma unroll
            for (int z = 0; z < 6; z++) s += P1[(size_t)z * total + idx];
            vals[c] = s;
            if (c >= NL_ && c < NL_ + DS_)
                relb[(size_t)b * DS_ + (c - NL_)] = __float2bfloat16_rn(s);
        }
        __syncthreads();
        float s = 0.f;
        for (int c = NL_ + tid; c < NL_ + DS_; c += 256) { float v = vals[c]; s += v * v; }
        red[tid] = s; __syncthreads();
        for (int st = 128; st > 0; st >>= 1) {
            if (tid < st) red[tid] += red[tid + st];
            __syncthreads();
        }
        if (tid == 0) {
            norms[b] = 1.f / fmaxf(sqrtf(red[0]), EPS_);
            float mx = -INFINITY;
            for (int j = 0; j < NL_; j++) mx = fmaxf(mx, vals[j]);
            float se = 0.f;
            for (int j = 0; j < NL_; j++) se += expf(vals[j] - mx);
            ce[b] = mx + logf(se) - vals[lab[b]];
        }
        return;
    }

    float s = 0.f;
    if (which == 1) {
        const float* x = rdesc + (size_t)b * DS_;
        for (int i = tid; i < DS_; i += 256) { float v = x[i]; s += v * v; }
    } else {
        const __nv_bfloat162* x = (const __nv_bfloat162*)
            (Db + (size_t)b * 4 * H_ + (which == 3 ? 2 * H_ : 0));
        for (int i = tid; i < H_; i += 256) {
            float2 v = __bfloat1622float2(x[i]);
            s += v.x * v.x + v.y * v.y;
        }
    }
    red[tid] = s; __syncthreads();
    for (int st = 128; st > 0; st >>= 1) {
        if (tid < st) red[tid] += red[tid + st];
        __syncthreads();
    }
    if (tid == 0) norms[which * B_ + b] = 1.f / fmaxf(sqrtf(red[0]), EPS_);
}

// ---------------- fused margin on P2 partials ----------------
__global__ void margin_fused(const float* __restrict__ P2, const float* __restrict__ norms,
                             const int* __restrict__ lab, float* __restrict__ mout)
{
    const int b = blockIdx.x, tid = threadIdx.x;
    __shared__ float vals[B_];
    __shared__ float red[256];
    const float rsA = norms[b];
    for (int j = tid; j < B_; j += 256) {
        float s = 0.f;
        const int idx = b * B_ + j;
#pragma unroll
        for (int z = 0; z < 6; z++) s += P2[(size_t)z * B_ * B_ + idx];
        vals[j] = s * rsA * norms[B_ + j];
    }
    __syncthreads();
    const int lb = lab[b];
    float mx = -INFINITY;
    for (int j = tid; j < B_; j += 256)
        if (lab[j] != lb) mx = fmaxf(mx, vals[j]);
    red[tid] = mx; __syncthreads();
    for (int st = 128; st > 0; st >>= 1) {
        if (tid < st) red[tid] = fmaxf(red[tid], red[tid + st]);
        __syncthreads();
    }
    if (tid == 0) {
        float neg = fmaxf(red[0], 0.f);
        mout[b] = fmaxf(neg - vals[b] + GAMMA_, 0.f) * (1.0f - ALPHA_);
    }
}

// ---------------- fused cl on P3 partials ----------------
__global__ void cl_fused(const float* __restrict__ P3, const float* __restrict__ norms,
                         float* __restrict__ cl)
{
    const int b = blockIdx.x, tid = threadIdx.x;
    __shared__ float vals[B_];
    __shared__ float red[256];
    const float rsA = norms[2 * B_ + b] * TEMP_INV_;
    for (int j = tid; j < B_; j += 256) {
        float s = 0.f;
        const int idx = b * B_ + j;
#pragma unroll
        for (int z = 0; z < 6; z++) s += P3[(size_t)z * B_ * B_ + idx];
        vals[j] = s * rsA * norms[3 * B_ + j];
    }
    __syncthreads();
    float mx = -INFINITY;
    for (int j = tid; j < B_; j += 256) mx = fmaxf(mx, vals[j]);
    red[tid] = mx; __syncthreads();
    for (int st = 128; st > 0; st >>= 1) {
        if (tid < st) red[tid] = fmaxf(red[tid], red[tid + st]);
        __syncthreads();
    }
    float m = red[0]; __syncthreads();
    float s = 0.f;
    for (int j = tid; j < B_; j += 256) s += expf(vals[j] - m);
    red[tid] = s; __syncthreads();
    for (int st = 128; st > 0; st >>= 1) {
        if (tid < st) red[tid] += red[tid + st];
        __syncthreads();
    }
    if (tid == 0) cl[b] = m + logf(red[0]) - vals[b];
}

// ---------------- final combine ----------------
__global__ void final_kernel(const float* __restrict__ ce, const float* __restrict__ m,
                             const float* __restrict__ cl, float* __restrict__ out)
{
    int tid = threadIdx.x;
    float v = ce[tid] * (1.0f / B_) + m[tid] + (ALPHA_ / B_) * cl[tid];
    __shared__ float red[512];
    red[tid] = v; __syncthreads();
    for (int st = 256; st > 0; st >>= 1) {
        if (tid < st) red[tid] += red[tid + st];
        __syncthreads();
    }
    if (tid == 0) out[0] = red[0];
}

// ---------------- host launcher ----------------
extern "C" void kernel_launch(void* const* d_in, const int* in_sizes, int n_in,
                              void* d_out, int out_size)
{
    const float* bert    = (const float*)d_in[0];
    const float* rdesc   = (const float*)d_in[1];
    const float* dense_w = (const float*)d_in[2];
    const float* dense_b = (const float*)d_in[3];
    const float* cls_w   = (const float*)d_in[4];
    const float* cls_b   = (const float*)d_in[5];
    const float* fc_w    = (const float*)d_in[6];
    const float* fc_b    = (const float*)d_in[7];
    const int*   eidx    = (const int*)d_in[8];
    const int*   lab     = (const int*)d_in[9];
    float* out = (float*)d_out;

    __nv_bfloat16 *RHb,*TOKSb,*Wd,*Wp,*rdescb,*relb,*Db;
    float *biasP,*P1,*P2,*P3,*norms,*ce,*mm,*cl;
    cudaGetSymbolAddress((void**)&RHb,    g_RHb);
    cudaGetSymbolAddress((void**)&TOKSb,  g_TOKSb);
    cudaGetSymbolAddress((void**)&Wd,     g_Wd);
    cudaGetSymbolAddress((void**)&Wp,     g_Wp);
    cudaGetSymbolAddress((void**)&rdescb, g_rdescb);
    cudaGetSymbolAddress((void**)&relb,   g_relb);
    cudaGetSymbolAddress((void**)&Db,     g_Db);
    cudaGetSymbolAddress((void**)&biasP,  g_biasP);
    cudaGetSymbolAddress((void**)&P1,     g_P1);
    cudaGetSymbolAddress((void**)&P2,     g_P2);
    cudaGetSymbolAddress((void**)&P3,     g_P3);
    cudaGetSymbolAddress((void**)&norms,  g_norms);
    cudaGetSymbolAddress((void**)&ce,     g_ce);
    cudaGetSymbolAddress((void**)&mm,     g_m);
    cudaGetSymbolAddress((void**)&cl,     g_cl);

    cudaFuncSetAttribute(mma_nt<0>, cudaFuncAttributeMaxDynamicSharedMemorySize, DYN_SMEM_BYTES_);
    cudaFuncSetAttribute(mma_nt<1>, cudaFuncAttributeMaxDynamicSharedMemorySize, DYN_SMEM_BYTES_);

    // prep
    gather_kernel<<<B_, 192>>>(bert, eidx, RHb, TOKSb);
    pack_kernel<<<592, 256>>>(dense_w, cls_w, fc_w, cls_b, fc_b, rdesc,
                              Wd, Wp, rdescb, biasP);

    // dense (NT): tanh(TOKSb @ Wd^T + b) -> Db bf16   [2048 x 768, K=768]
    mma_nt<1><<<dim3(12, 16, 1), 256, DYN_SMEM_BYTES_>>>(TOKSb, Wd, nullptr, dense_b, Db,
        4*B_, H_, H_, H_, H_, H_, H_);

    // packed (NT): RHb @ Wp^T -> P1 (split-K 6)   [512 x 448, K=2304]
    mma_nt<0><<<dim3(7, 4, 6), 256, DYN_SMEM_BYTES_>>>(RHb, Wp, P1, nullptr, nullptr,
        B_, NP2_, H3_, H3_, H3_, NP2_, 384);

    // fused reduce + bias + CE + all norms
    post_kernel<<<dim3(B_, 4), 256>>>(P1, biasP, rdesc, Db, lab, relb, norms, ce);

    // C (NT): rel @ rdesc^T (split-K 6)   [512 x 512, K=384]
    mma_nt<0><<<dim3(8, 4, 6), 256, DYN_SMEM_BYTES_>>>(relb, rdescb, P2, nullptr, nullptr,
        B_, B_, DS_, DS_, DS_, B_, 64);

    // cos (NT): z1 @ z2^T (split-K 6)   [512 x 512, K=1536]
    mma_nt<0><<<dim3(8, 4, 6), 256, DYN_SMEM_BYTES_>>>(Db, Db + 2*H_, P3, nullptr, nullptr,
        B_, B_, 2*H_, 4*H_, 4*H_, B_, 256);

    // fused losses on partials
    margin_fused<<<B_, 256>>>(P2, norms, lab, mm);
    cl_fused<<<B_, 256>>>(P3, norms, cl);
    final_kernel<<<1, 512>>>(ce, mm, cl, out);
}

// round 12
// speedup vs baseline: 1.0516x; 1.0516x over previous
#include <cuda_runtime.h>
#include <cuda_bf16.h>
#include <math.h>
#include <stdint.h>

#define B_    512
#define S_    128
#define H_    768
#define DS_   384
#define NL_   40
#define H3_   2304
#define NP2_  448          // packed N padded to 7*64
#define TEMP_INV_ 20.0f
#define ALPHA_    0.15f
#define GAMMA_    7.5f
#define EPS_      1e-8f

// ---------------- scratch ----------------
__device__ __nv_bfloat16 g_RHb[B_ * H3_];        // tanh(concat) bf16  512x2304
__device__ __nv_bfloat16 g_TOKSb[B_ * 4 * H_];   // bf16 2048x768
__device__ __nv_bfloat16 g_Wd[H_ * H_];          // dense_w^T bf16 [N=768, K=768]
__device__ __nv_bfloat16 g_Wp[NP2_ * H3_];       // packed W^T bf16 [N=448, K=2304]
__device__ __nv_bfloat16 g_rdescb[B_ * DS_];     // rdesc bf16
__device__ __nv_bfloat16 g_relb[B_ * DS_];       // rel bf16
__device__ __nv_bfloat16 g_Db[B_ * 4 * H_];      // tanh dense out bf16 2048x768
__device__ float g_biasP[NP2_];
__device__ float g_P1[6 * B_ * NP2_];            // packed partials
__device__ float g_P2[6 * B_ * B_];              // C partials
__device__ float g_P3[6 * B_ * B_];              // cos partials
__device__ float g_norms[4 * B_];                // recip norms: rel, rdesc, z1, z2
__device__ float g_ce[B_];
__device__ float g_m[B_];
__device__ float g_cl[B_];

__device__ __forceinline__ uint32_t smem_u32(const void* p) {
    uint32_t a;
    asm("{ .reg .u64 t; cvta.to.shared.u64 t, %1; cvt.u32.u64 %0, t; }" : "=r"(a) : "l"(p));
    return a;
}

// ================= mma.sync bf16 NT GEMM, 2-stage cp.async, 2 CTAs/SM =================
// D tile 128x64 = A[M,K](bf16 rm, lda) @ B[N,K]^T (bf16 rm, ldb)
// K from kBeg=z*kChunk, kChunk % 64 == 0. 8 warps 4(M)x2(N), warp tile 32x32.
// MODE 0: raw fp32 -> C + z*M*ldc ; MODE 1: tanh(acc+bias) -> Obf bf16 only
#define KT_ 64
#define SPAD_ 72
#define STAGE_ELEMS_ ((128 + 64) * SPAD_)
#define NSTAGE_ 2
#define DYN_SMEM_BYTES_ (NSTAGE_ * STAGE_ELEMS_ * 2)

template<int MODE>
__global__ __launch_bounds__(256, 2)
void mma_nt(const __nv_bfloat16* __restrict__ A, const __nv_bfloat16* __restrict__ B,
            float* __restrict__ C, const float* __restrict__ bias,
            __nv_bfloat16* __restrict__ Obf,
            int M, int N, int K, int lda, int ldb, int ldc, int kChunk)
{
    extern __shared__ __nv_bfloat16 dyn[];

    const int tid  = threadIdx.x;
    const int warp = tid >> 5, lane = tid & 31;
    const int wm = warp >> 1, wn = warp & 1;
    const int bm = blockIdx.y * 128, bn = blockIdx.x * 64;
    const int kBeg = blockIdx.z * kChunk;

    const int arow = tid >> 1, ac0 = (tid & 1) * 32;   // A: 4 x 16B per thread
    const __nv_bfloat16* Ag = A + (size_t)(bm + arow) * lda + ac0;
    const int brow = tid >> 2, bc0 = (tid & 3) * 16;   // B: 2 x 16B per thread
    const __nv_bfloat16* Bg = B + (size_t)(bn + brow) * ldb + bc0;

    const int alr = lane & 15, alc = (lane >> 4) << 3;
    const int blr = lane & 7,  blc = ((lane >> 3) & 1) << 3;

    float acc[2][4][4];
#pragma unroll
    for (int mi = 0; mi < 2; mi++)
#pragma unroll
        for (int ni = 0; ni < 4; ni++)
#pragma unroll
            for (int r = 0; r < 4; r++) acc[mi][ni][r] = 0.f;

    const int nTiles = kChunk / KT_;

    auto stage = [&](int t) {
        __nv_bfloat16* buf = dyn + (t & 1) * STAGE_ELEMS_;
        const int k0 = kBeg + t * KT_;
        uint32_t sa = smem_u32(buf + arow * SPAD_ + ac0);
        const __nv_bfloat16* ag = Ag + k0;
#pragma unroll
        for (int j = 0; j < 4; j++)
            asm volatile("cp.async.cg.shared.global [%0], [%1], 16;"
                         :: "r"(sa + j * 16), "l"(ag + j * 8) : "memory");
        uint32_t sb = smem_u32(buf + 128 * SPAD_ + brow * SPAD_ + bc0);
        const __nv_bfloat16* bg = Bg + k0;
#pragma unroll
        for (int j = 0; j < 2; j++)
            asm volatile("cp.async.cg.shared.global [%0], [%1], 16;"
                         :: "r"(sb + j * 16), "l"(bg + j * 8) : "memory");
        asm volatile("cp.async.commit_group;" ::: "memory");
    };

    stage(0);
    if (nTiles > 1) stage(1);

    for (int t = 0; t < nTiles; t++) {
        // groups committed: up to t+1 ; allow 1 pending unless last tile
        if (nTiles - 1 - t >= 1) asm volatile("cp.async.wait_group 1;" ::: "memory");
        else                     asm volatile("cp.async.wait_group 0;" ::: "memory");
        __syncthreads();

        const __nv_bfloat16* cA = dyn + (t & 1) * STAGE_ELEMS_;
        const __nv_bfloat16* cB = cA + 128 * SPAD_;
#pragma unroll
        for (int ks = 0; ks < KT_ / 16; ks++) {
            const int kk = ks * 16;
            uint32_t a[2][4], b[4][2];
#pragma unroll
            for (int mi = 0; mi < 2; mi++) {
                uint32_t addr = smem_u32(cA + (wm * 32 + mi * 16 + alr) * SPAD_ + kk + alc);
                asm volatile("ldmatrix.sync.aligned.m8n8.x4.shared.b16 {%0,%1,%2,%3}, [%4];"
                             : "=r"(a[mi][0]), "=r"(a[mi][1]), "=r"(a[mi][2]), "=r"(a[mi][3])
                             : "r"(addr));
            }
#pragma unroll
            for (int ni = 0; ni < 4; ni++) {
                uint32_t addr = smem_u32(cB + (wn * 32 + ni * 8 + blr) * SPAD_ + kk + blc);
                asm volatile("ldmatrix.sync.aligned.m8n8.x2.shared.b16 {%0,%1}, [%2];"
                             : "=r"(b[ni][0]), "=r"(b[ni][1]) : "r"(addr));
            }
#pragma unroll
            for (int mi = 0; mi < 2; mi++)
#pragma unroll
                for (int ni = 0; ni < 4; ni++) {
                    asm volatile(
                        "mma.sync.aligned.m16n8k16.row.col.f32.bf16.bf16.f32 "
                        "{%0,%1,%2,%3}, {%4,%5,%6,%7}, {%8,%9}, {%0,%1,%2,%3};"
                        : "+f"(acc[mi][ni][0]), "+f"(acc[mi][ni][1]),
                          "+f"(acc[mi][ni][2]), "+f"(acc[mi][ni][3])
                        : "r"(a[mi][0]), "r"(a[mi][1]), "r"(a[mi][2]), "r"(a[mi][3]),
                          "r"(b[ni][0]), "r"(b[ni][1]));
                }
        }

        if (t + 2 < nTiles) {
            __syncthreads();           // buffer (t+2)&1 == t&1 was just read
            stage(t + 2);
        }
    }

    const int g = lane >> 2, cpair = (lane & 3) * 2;
#pragma unroll
    for (int mi = 0; mi < 2; mi++) {
#pragma unroll
        for (int half = 0; half < 2; half++) {
            const int row = bm + wm * 32 + mi * 16 + g + half * 8;
#pragma unroll
            for (int ni = 0; ni < 4; ni++) {
                const int col = bn + wn * 32 + ni * 8 + cpair;
                float v0 = acc[mi][ni][half * 2 + 0];
                float v1 = acc[mi][ni][half * 2 + 1];
                if (MODE == 0) {
                    float* Co = C + (size_t)blockIdx.z * M * ldc + (size_t)row * ldc + col;
                    Co[0] = v0; Co[1] = v1;
                } else {
                    float t0 = tanhf(v0 + bias[col]);
                    float t1 = tanhf(v1 + bias[col + 1]);
                    *(__nv_bfloat162*)(Obf + (size_t)row * ldc + col) =
                        __floats2bfloat162_rn(t0, t1);
                }
            }
        }
    }
}

// ---------------- gather + tanh -> bf16 ----------------
__global__ void gather_kernel(const float* __restrict__ bert,
                              const int* __restrict__ eidx,
                              __nv_bfloat16* __restrict__ RHb,
                              __nv_bfloat16* __restrict__ TOKSb)
{
    int b = blockIdx.x, t = threadIdx.x;  // 0..191
    const float* base0 = bert + (size_t)b * 2 * S_ * H_;
    const float* base1 = base0 + S_ * H_;
    int i0 = eidx[b*4+0], i1 = eidx[b*4+1], i2 = eidx[b*4+2], i3 = eidx[b*4+3];
    float4 c  = ((const float4*)base0)[t];
    float4 hh = ((const float4*)(base0 + (size_t)i0*H_))[t];
    float4 tl = ((const float4*)(base0 + (size_t)i1*H_))[t];
    float4 a2 = ((const float4*)(base1 + (size_t)i2*H_))[t];
    float4 b2 = ((const float4*)(base1 + (size_t)i3*H_))[t];

    __nv_bfloat162* rh = (__nv_bfloat162*)(RHb + (size_t)b * H3_);
    __nv_bfloat162* tk = (__nv_bfloat162*)(TOKSb + (size_t)b * 4 * H_);
    rh[2*t]       = __floats2bfloat162_rn(tanhf(c.x),  tanhf(c.y));
    rh[2*t+1]     = __floats2bfloat162_rn(tanhf(c.z),  tanhf(c.w));
    rh[384+2*t]   = __floats2bfloat162_rn(tanhf(hh.x), tanhf(hh.y));
    rh[384+2*t+1] = __floats2bfloat162_rn(tanhf(hh.z), tanhf(hh.w));
    rh[768+2*t]   = __floats2bfloat162_rn(tanhf(tl.x), tanhf(tl.y));
    rh[768+2*t+1] = __floats2bfloat162_rn(tanhf(tl.z), tanhf(tl.w));
    tk[2*t]        = __floats2bfloat162_rn(hh.x, hh.y);
    tk[2*t+1]      = __floats2bfloat162_rn(hh.z, hh.w);
    tk[384+2*t]    = __floats2bfloat162_rn(tl.x, tl.y);
    tk[384+2*t+1]  = __floats2bfloat162_rn(tl.z, tl.w);
    tk[768+2*t]    = __floats2bfloat162_rn(a2.x, a2.y);
    tk[768+2*t+1]  = __floats2bfloat162_rn(a2.z, a2.w);
    tk[1152+2*t]   = __floats2bfloat162_rn(b2.x, b2.y);
    tk[1152+2*t+1] = __floats2bfloat162_rn(b2.z, b2.w);
}

// ---------------- coalesced tiled transpose: dense_w [K,N] f32 -> Wd [N,K] bf16 ----------------
__global__ void trans_dense(const float* __restrict__ src, __nv_bfloat16* __restrict__ dst)
{
    __shared__ float s[32][33];
    const int k0 = blockIdx.x * 32, n0 = blockIdx.y * 32;
    const int tx = threadIdx.x, ty = threadIdx.y;   // 32 x 8
#pragma unroll
    for (int j = 0; j < 32; j += 8)
        s[ty + j][tx] = src[(size_t)(k0 + ty + j) * H_ + n0 + tx];
    __syncthreads();
#pragma unroll
    for (int j = 0; j < 32; j += 8)
        dst[(size_t)(n0 + ty + j) * H_ + k0 + tx] = __float2bfloat16_rn(s[tx][ty + j]);
}

// ---------------- coalesced tiled transpose: packed (cls_w|fc_w) -> Wp [448,2304] bf16 ----------------
__global__ void trans_packw(const float* __restrict__ cls_w, const float* __restrict__ fc_w,
                            __nv_bfloat16* __restrict__ dst)
{
    __shared__ float s[32][33];
    const int k0 = blockIdx.x * 32, n0 = blockIdx.y * 32;
    const int tx = threadIdx.x, ty = threadIdx.y;
#pragma unroll
    for (int j = 0; j < 32; j += 8) {
        const int k = k0 + ty + j, n = n0 + tx;
        float v = 0.f;
        if (n < NL_)            v = cls_w[(size_t)k * NL_ + n];
        else if (n < NL_ + DS_) v = fc_w[(size_t)k * DS_ + (n - NL_)];
        s[ty + j][tx] = v;
    }
    __syncthreads();
#pragma unroll
    for (int j = 0; j < 32; j += 8)
        dst[(size_t)(n0 + ty + j) * H3_ + k0 + tx] = __float2bfloat16_rn(s[tx][ty + j]);
}

// ---------------- misc: rdesc convert + packed bias ----------------
__global__ void pack_misc(const float* __restrict__ rdesc,
                          const float* __restrict__ cls_b, const float* __restrict__ fc_b,
                          __nv_bfloat16* __restrict__ rdescb, float* __restrict__ biasP)
{
    int idx = blockIdx.x * blockDim.x + threadIdx.x;
    if (idx < B_ * DS_) rdescb[idx] = __float2bfloat16_rn(rdesc[idx]);
    if (idx < NP2_)
        biasP[idx] = (idx < NL_) ? cls_b[idx] : ((idx < NL_ + DS_) ? fc_b[idx - NL_] : 0.f);
}

// ---------------- fused post-GEMM: reduce P1 + bias + CE + all norms ----------------
__global__ void post_kernel(const float* __restrict__ P1, const float* __restrict__ biasP,
                            const float* __restrict__ rdesc, const __nv_bfloat16* __restrict__ Db,
                            const int* __restrict__ lab,
                            __nv_bfloat16* __restrict__ relb,
                            float* __restrict__ norms, float* __restrict__ ce)
{
    const int b = blockIdx.x, which = blockIdx.y, tid = threadIdx.x;
    __shared__ float red[256];
    __shared__ float vals[NP2_];

    if (which == 0) {
        const int total = B_ * NP2_;
        for (int c = tid; c < NP2_; c += 256) {
            float s = biasP[c];
            int idx = b * NP2_ + c;
#pragma unroll
            for (int z = 0; z < 6; z++) s += P1[(size_t)z * total + idx];
            vals[c] = s;
            if (c >= NL_ && c < NL_ + DS_)
                relb[(size_t)b * DS_ + (c - NL_)] = __float2bfloat16_rn(s);
        }
        __syncthreads();
        float s = 0.f;
        for (int c = NL_ + tid; c < NL_ + DS_; c += 256) { float v = vals[c]; s += v * v; }
        red[tid] = s; __syncthreads();
        for (int st = 128; st > 0; st >>= 1) {
            if (tid < st) red[tid] += red[tid + st];
            __syncthreads();
        }
        if (tid == 0) {
            norms[b] = 1.f / fmaxf(sqrtf(red[0]), EPS_);
            float mx = -INFINITY;
            for (int j = 0; j < NL_; j++) mx = fmaxf(mx, vals[j]);
            float se = 0.f;
            for (int j = 0; j < NL_; j++) se += expf(vals[j] - mx);
            ce[b] = mx + logf(se) - vals[lab[b]];
        }
        return;
    }

    float s = 0.f;
    if (which == 1) {
        const float* x = rdesc + (size_t)b * DS_;
        for (int i = tid; i < DS_; i += 256) { float v = x[i]; s += v * v; }
    } else {
        const __nv_bfloat162* x = (const __nv_bfloat162*)
            (Db + (size_t)b * 4 * H_ + (which == 3 ? 2 * H_ : 0));
        for (int i = tid; i < H_; i += 256) {
            float2 v = __bfloat1622float2(x[i]);
            s += v.x * v.x + v.y * v.y;
        }
    }
    red[tid] = s; __syncthreads();
    for (int st = 128; st > 0; st >>= 1) {
        if (tid < st) red[tid] += red[tid + st];
        __syncthreads();
    }
    if (tid == 0) norms[which * B_ + b] = 1.f / fmaxf(sqrtf(red[0]), EPS_);
}

// ---------------- fused margin on P2 partials ----------------
__global__ void margin_fused(const float* __restrict__ P2, const float* __restrict__ norms,
                             const int* __restrict__ lab, float* __restrict__ mout)
{
    const int b = blockIdx.x, tid = threadIdx.x;
    __shared__ float vals[B_];
    __shared__ float red[256];
    const float rsA = norms[b];
    for (int j = tid; j < B_; j += 256) {
        float s = 0.f;
        const int idx = b * B_ + j;
#pragma unroll
        for (int z = 0; z < 6; z++) s += P2[(size_t)z * B_ * B_ + idx];
        vals[j] = s * rsA * norms[B_ + j];
    }
    __syncthreads();
    const int lb = lab[b];
    float mx = -INFINITY;
    for (int j = tid; j < B_; j += 256)
        if (lab[j] != lb) mx = fmaxf(mx, vals[j]);
    red[tid] = mx; __syncthreads();
    for (int st = 128; st > 0; st >>= 1) {
        if (tid < st) red[tid] = fmaxf(red[tid], red[tid + st]);
        __syncthreads();
    }
    if (tid == 0) {
        float neg = fmaxf(red[0], 0.f);
        mout[b] = fmaxf(neg - vals[b] + GAMMA_, 0.f) * (1.0f - ALPHA_);
    }
}

// ---------------- fused cl on P3 partials ----------------
__global__ void cl_fused(const float* __restrict__ P3, const float* __restrict__ norms,
                         float* __restrict__ cl)
{
    const int b = blockIdx.x, tid = threadIdx.x;
    __shared__ float vals[B_];
    __shared__ float red[256];
    const float rsA = norms[2 * B_ + b] * TEMP_INV_;
    for (int j = tid; j < B_; j += 256) {
        float s = 0.f;
        const int idx = b * B_ + j;
#pragma unroll
        for (int z = 0; z < 6; z++) s += P3[(size_t)z * B_ * B_ + idx];
        vals[j] = s * rsA * norms[3 * B_ + j];
    }
    __syncthreads();
    float mx = -INFINITY;
    for (int j = tid; j < B_; j += 256) mx = fmaxf(mx, vals[j]);
    red[tid] = mx; __syncthreads();
    for (int st = 128; st > 0; st >>= 1) {
        if (tid < st) red[tid] = fmaxf(red[tid], red[tid + st]);
        __syncthreads();
    }
    float m = red[0]; __syncthreads();
    float s = 0.f;
    for (int j = tid; j < B_; j += 256) s += expf(vals[j] - m);
    red[tid] = s; __syncthreads();
    for (int st = 128; st > 0; st >>= 1) {
        if (tid < st) red[tid] += red[tid + st];
        __syncthreads();
    }
    if (tid == 0) cl[b] = m + logf(red[0]) - vals[b];
}

// ---------------- final combine ----------------
__global__ void final_kernel(const float* __restrict__ ce, const float* __restrict__ m,
                             const float* __restrict__ cl, float* __restrict__ out)
{
    int tid = threadIdx.x;
    float v = ce[tid] * (1.0f / B_) + m[tid] + (ALPHA_ / B_) * cl[tid];
    __shared__ float red[512];
    red[tid] = v; __syncthreads();
    for (int st = 256; st > 0; st >>= 1) {
        if (tid < st) red[tid] += red[tid + st];
        __syncthreads();
    }
    if (tid == 0) out[0] = red[0];
}

// ---------------- host launcher ----------------
extern "C" void kernel_launch(void* const* d_in, const int* in_sizes, int n_in,
                              void* d_out, int out_size)
{
    const float* bert    = (const float*)d_in[0];
    const float* rdesc   = (const float*)d_in[1];
    const float* dense_w = (const float*)d_in[2];
    const float* dense_b = (const float*)d_in[3];
    const float* cls_w   = (const float*)d_in[4];
    const float* cls_b   = (const float*)d_in[5];
    const float* fc_w    = (const float*)d_in[6];
    const float* fc_b    = (const float*)d_in[7];
    const int*   eidx    = (const int*)d_in[8];
    const int*   lab     = (const int*)d_in[9];
    float* out = (float*)d_out;

    __nv_bfloat16 *RHb,*TOKSb,*Wd,*Wp,*rdescb,*relb,*Db;
    float *biasP,*P1,*P2,*P3,*norms,*ce,*mm,*cl;
    cudaGetSymbolAddress((void**)&RHb,    g_RHb);
    cudaGetSymbolAddress((void**)&TOKSb,  g_TOKSb);
    cudaGetSymbolAddress((void**)&Wd,     g_Wd);
    cudaGetSymbolAddress((void**)&Wp,     g_Wp);
    cudaGetSymbolAddress((void**)&rdescb, g_rdescb);
    cudaGetSymbolAddress((void**)&relb,   g_relb);
    cudaGetSymbolAddress((void**)&Db,     g_Db);
    cudaGetSymbolAddress((void**)&biasP,  g_biasP);
    cudaGetSymbolAddress((void**)&P1,     g_P1);
    cudaGetSymbolAddress((void**)&P2,     g_P2);
    cudaGetSymbolAddress((void**)&P3,     g_P3);
    cudaGetSymbolAddress((void**)&norms,  g_norms);
    cudaGetSymbolAddress((void**)&ce,     g_ce);
    cudaGetSymbolAddress((void**)&mm,     g_m);
    cudaGetSymbolAddress((void**)&cl,     g_cl);

    cudaFuncSetAttribute(mma_nt<0>, cudaFuncAttributeMaxDynamicSharedMemorySize, DYN_SMEM_BYTES_);
    cudaFuncSetAttribute(mma_nt<1>, cudaFuncAttributeMaxDynamicSharedMemorySize, DYN_SMEM_BYTES_);

    // prep (independent, coalesced)
    gather_kernel<<<B_, 192>>>(bert, eidx, RHb, TOKSb);
    trans_dense<<<dim3(24, 24), dim3(32, 8)>>>(dense_w, Wd);
    trans_packw<<<dim3(72, 14), dim3(32, 8)>>>(cls_w, fc_w, Wp);
    pack_misc<<<(B_*DS_ + 255)/256, 256>>>(rdesc, cls_b, fc_b, rdescb, biasP);

    // dense (NT): tanh(TOKSb @ Wd^T + b) -> Db bf16   [2048 x 768, K=768]  (192 CTAs, 1 wave @2/SM)
    mma_nt<1><<<dim3(12, 16, 1), 256, DYN_SMEM_BYTES_>>>(TOKSb, Wd, nullptr, dense_b, Db,
        4*B_, H_, H_, H_, H_, H_, H_);

    // packed (NT): RHb @ Wp^T -> P1 (split-K 6)   [512 x 448, K=2304]  (168 CTAs)
    mma_nt<0><<<dim3(7, 4, 6), 256, DYN_SMEM_BYTES_>>>(RHb, Wp, P1, nullptr, nullptr,
        B_, NP2_, H3_, H3_, H3_, NP2_, 384);

    // fused reduce + bias + CE + all norms
    post_kernel<<<dim3(B_, 4), 256>>>(P1, biasP, rdesc, Db, lab, relb, norms, ce);

    // C (NT): rel @ rdesc^T (split-K 6)   [512 x 512, K=384]  (192 CTAs)
    mma_nt<0><<<dim3(8, 4, 6), 256, DYN_SMEM_BYTES_>>>(relb, rdescb, P2, nullptr, nullptr,
        B_, B_, DS_, DS_, DS_, B_, 64);

    // cos (NT): z1 @ z2^T (split-K 6)   [512 x 512, K=1536]  (192 CTAs)
    mma_nt<0><<<dim3(8, 4, 6), 256, DYN_SMEM_BYTES_>>>(Db, Db + 2*H_, P3, nullptr, nullptr,
        B_, B_, 2*H_, 4*H_, 4*H_, B_, 256);

    // fused losses on partials
    margin_fused<<<B_, 256>>>(P2, norms, lab, mm);
    cl_fused<<<B_, 256>>>(P3, norms, cl);
    final_kernel<<<1, 512>>>(ce, mm, cl, out);
}

// round 15
// speedup vs baseline: 1.3240x; 1.2590x over previous
#include <cuda_runtime.h>
#include <cuda_bf16.h>
#include <math.h>
#include <stdint.h>

#define B_    512
#define S_    128
#define H_    768
#define DS_   384
#define NL_   40
#define H3_   2304
#define NP2_  448          // packed N padded to 7*64
#define TEMP_INV_ 20.0f
#define ALPHA_    0.15f
#define GAMMA_    7.5f
#define EPS_      1e-8f

// ---------------- scratch ----------------
__device__ __nv_bfloat16 g_RHb[B_ * H3_];
__device__ __nv_bfloat16 g_TOKSb[B_ * 4 * H_];
__device__ __nv_bfloat16 g_Wd[H_ * H_];          // dense_w^T bf16 [N,K]
__device__ __nv_bfloat16 g_Wp[NP2_ * H3_];       // packed W^T bf16 [448,2304]
__device__ __nv_bfloat16 g_rdescb[B_ * DS_];
__device__ __nv_bfloat16 g_relb[B_ * DS_];
__device__ __nv_bfloat16 g_Db[B_ * 4 * H_];
__device__ float g_biasP[NP2_];
__device__ float g_P1[6 * B_ * NP2_];
__device__ float g_P2[6 * B_ * B_];
__device__ float g_P3[6 * B_ * B_];
__device__ float g_norms[4 * B_];
__device__ float g_ce[B_];
__device__ float g_m[B_];
__device__ float g_cl[B_];

__device__ __forceinline__ uint32_t smem_u32(const void* p) {
    uint32_t a;
    asm("{ .reg .u64 t; cvta.to.shared.u64 t, %1; cvt.u32.u64 %0, t; }" : "=r"(a) : "l"(p));
    return a;
}

// ================= mma.sync bf16 NT GEMM (unchanged, passing since R12) =================
#define KT_ 64
#define SPAD_ 72
#define STAGE_ELEMS_ ((128 + 64) * SPAD_)
#define NSTAGE_ 2
#define DYN_SMEM_BYTES_ (NSTAGE_ * STAGE_ELEMS_ * 2)

template<int MODE>
__global__ __launch_bounds__(256, 2)
void mma_nt(const __nv_bfloat16* __restrict__ A, const __nv_bfloat16* __restrict__ B,
            float* __restrict__ C, const float* __restrict__ bias,
            __nv_bfloat16* __restrict__ Obf,
            int M, int N, int K, int lda, int ldb, int ldc, int kChunk)
{
    extern __shared__ __nv_bfloat16 dyn[];

    const int tid  = threadIdx.x;
    const int warp = tid >> 5, lane = tid & 31;
    const int wm = warp >> 1, wn = warp & 1;
    const int bm = blockIdx.y * 128, bn = blockIdx.x * 64;
    const int kBeg = blockIdx.z * kChunk;

    const int arow = tid >> 1, ac0 = (tid & 1) * 32;
    const __nv_bfloat16* Ag = A + (size_t)(bm + arow) * lda + ac0;
    const int brow = tid >> 2, bc0 = (tid & 3) * 16;
    const __nv_bfloat16* Bg = B + (size_t)(bn + brow) * ldb + bc0;

    const int alr = lane & 15, alc = (lane >> 4) << 3;
    const int blr = lane & 7,  blc = ((lane >> 3) & 1) << 3;

    float acc[2][4][4];
#pragma unroll
    for (int mi = 0; mi < 2; mi++)
#pragma unroll
        for (int ni = 0; ni < 4; ni++)
#pragma unroll
            for (int r = 0; r < 4; r++) acc[mi][ni][r] = 0.f;

    const int nTiles = kChunk / KT_;

    auto stage = [&](int t) {
        __nv_bfloat16* buf = dyn + (t & 1) * STAGE_ELEMS_;
        const int k0 = kBeg + t * KT_;
        uint32_t sa = smem_u32(buf + arow * SPAD_ + ac0);
        const __nv_bfloat16* ag = Ag + k0;
#pragma unroll
        for (int j = 0; j < 4; j++)
            asm volatile("cp.async.cg.shared.global [%0], [%1], 16;"
                         :: "r"(sa + j * 16), "l"(ag + j * 8) : "memory");
        uint32_t sb = smem_u32(buf + 128 * SPAD_ + brow * SPAD_ + bc0);
        const __nv_bfloat16* bg = Bg + k0;
#pragma unroll
        for (int j = 0; j < 2; j++)
            asm volatile("cp.async.cg.shared.global [%0], [%1], 16;"
                         :: "r"(sb + j * 16), "l"(bg + j * 8) : "memory");
        asm volatile("cp.async.commit_group;" ::: "memory");
    };

    stage(0);
    if (nTiles > 1) stage(1);

    for (int t = 0; t < nTiles; t++) {
        if (nTiles - 1 - t >= 1) asm volatile("cp.async.wait_group 1;" ::: "memory");
        else                     asm volatile("cp.async.wait_group 0;" ::: "memory");
        __syncthreads();

        const __nv_bfloat16* cA = dyn + (t & 1) * STAGE_ELEMS_;
        const __nv_bfloat16* cB = cA + 128 * SPAD_;
#pragma unroll
        for (int ks = 0; ks < KT_ / 16; ks++) {
            const int kk = ks * 16;
            uint32_t a[2][4], b[4][2];
#pragma unroll
            for (int mi = 0; mi < 2; mi++) {
                uint32_t addr = smem_u32(cA + (wm * 32 + mi * 16 + alr) * SPAD_ + kk + alc);
                asm volatile("ldmatrix.sync.aligned.m8n8.x4.shared.b16 {%0,%1,%2,%3}, [%4];"
                             : "=r"(a[mi][0]), "=r"(a[mi][1]), "=r"(a[mi][2]), "=r"(a[mi][3])
                             : "r"(addr));
            }
#pragma unroll
            for (int ni = 0; ni < 4; ni++) {
                uint32_t addr = smem_u32(cB + (wn * 32 + ni * 8 + blr) * SPAD_ + kk + blc);
                asm volatile("ldmatrix.sync.aligned.m8n8.x2.shared.b16 {%0,%1}, [%2];"
                             : "=r"(b[ni][0]), "=r"(b[ni][1]) : "r"(addr));
            }
#pragma unroll
            for (int mi = 0; mi < 2; mi++)
#pragma unroll
                for (int ni = 0; ni < 4; ni++) {
                    asm volatile(
                        "mma.sync.aligned.m16n8k16.row.col.f32.bf16.bf16.f32 "
                        "{%0,%1,%2,%3}, {%4,%5,%6,%7}, {%8,%9}, {%0,%1,%2,%3};"
                        : "+f"(acc[mi][ni][0]), "+f"(acc[mi][ni][1]),
                          "+f"(acc[mi][ni][2]), "+f"(acc[mi][ni][3])
                        : "r"(a[mi][0]), "r"(a[mi][1]), "r"(a[mi][2]), "r"(a[mi][3]),
                          "r"(b[ni][0]), "r"(b[ni][1]));
                }
        }

        if (t + 2 < nTiles) {
            __syncthreads();
            stage(t + 2);
        }
    }

    const int g = lane >> 2, cpair = (lane & 3) * 2;
#pragma unroll
    for (int mi = 0; mi < 2; mi++) {
#pragma unroll
        for (int half = 0; half < 2; half++) {
            const int row = bm + wm * 32 + mi * 16 + g + half * 8;
#pragma unroll
            for (int ni = 0; ni < 4; ni++) {
                const int col = bn + wn * 32 + ni * 8 + cpair;
                float v0 = acc[mi][ni][half * 2 + 0];
                float v1 = acc[mi][ni][half * 2 + 1];
                if (MODE == 0) {
                    float* Co = C + (size_t)blockIdx.z * M * ldc + (size_t)row * ldc + col;
                    Co[0] = v0; Co[1] = v1;
                } else {
                    float t0 = tanhf(v0 + bias[col]);
                    float t1 = tanhf(v1 + bias[col + 1]);
                    *(__nv_bfloat162*)(Obf + (size_t)row * ldc + col) =
                        __floats2bfloat162_rn(t0, t1);
                }
            }
        }
    }
}

// ---------------- gather + tanh -> bf16 ----------------
__global__ void gather_kernel(const float* __restrict__ bert,
                              const int* __restrict__ eidx,
                              __nv_bfloat16* __restrict__ RHb,
                              __nv_bfloat16* __restrict__ TOKSb)
{
    int b = blockIdx.x, t = threadIdx.x;  // 0..191
    const float* base0 = bert + (size_t)b * 2 * S_ * H_;
    const float* base1 = base0 + S_ * H_;
    int i0 = eidx[b*4+0], i1 = eidx[b*4+1], i2 = eidx[b*4+2], i3 = eidx[b*4+3];
    float4 c  = ((const float4*)base0)[t];
    float4 hh = ((const float4*)(base0 + (size_t)i0*H_))[t];
    float4 tl = ((const float4*)(base0 + (size_t)i1*H_))[t];
    float4 a2 = ((const float4*)(base1 + (size_t)i2*H_))[t];
    float4 b2 = ((const float4*)(base1 + (size_t)i3*H_))[t];

    __nv_bfloat162* rh = (__nv_bfloat162*)(RHb + (size_t)b * H3_);
    __nv_bfloat162* tk = (__nv_bfloat162*)(TOKSb + (size_t)b * 4 * H_);
    rh[2*t]       = __floats2bfloat162_rn(tanhf(c.x),  tanhf(c.y));
    rh[2*t+1]     = __floats2bfloat162_rn(tanhf(c.z),  tanhf(c.w));
    rh[384+2*t]   = __floats2bfloat162_rn(tanhf(hh.x), tanhf(hh.y));
    rh[384+2*t+1] = __floats2bfloat162_rn(tanhf(hh.z), tanhf(hh.w));
    rh[768+2*t]   = __floats2bfloat162_rn(tanhf(tl.x), tanhf(tl.y));
    rh[768+2*t+1] = __floats2bfloat162_rn(tanhf(tl.z), tanhf(tl.w));
    tk[2*t]        = __floats2bfloat162_rn(hh.x, hh.y);
    tk[2*t+1]      = __floats2bfloat162_rn(hh.z, hh.w);
    tk[384+2*t]    = __floats2bfloat162_rn(tl.x, tl.y);
    tk[384+2*t+1]  = __floats2bfloat162_rn(tl.z, tl.w);
    tk[768+2*t]    = __floats2bfloat162_rn(a2.x, a2.y);
    tk[768+2*t+1]  = __floats2bfloat162_rn(a2.z, a2.w);
    tk[1152+2*t]   = __floats2bfloat162_rn(b2.x, b2.y);
    tk[1152+2*t+1] = __floats2bfloat162_rn(b2.z, b2.w);
}

// ---------------- fused prep: weight transposes + rdesc convert + bias pack ----------------
// blocks [0,576): dense_w tiles; [576,1584): packed-w tiles; [1584,1968): rdesc pairs + bias
#define PREP_TD_ 576
#define PREP_TP_ 1008
#define PREP_MISC_ 384
#define PREP_BLOCKS_ (PREP_TD_ + PREP_TP_ + PREP_MISC_)
__global__ void prep_kernel(const float* __restrict__ dense_w,
                            const float* __restrict__ cls_w, const float* __restrict__ fc_w,
                            const float* __restrict__ cls_b, const float* __restrict__ fc_b,
                            const float* __restrict__ rdesc,
                            __nv_bfloat16* __restrict__ Wd, __nv_bfloat16* __restrict__ Wp,
                            __nv_bfloat16* __restrict__ rdescb, float* __restrict__ biasP)
{
    __shared__ float s[32][33];
    const int tx = threadIdx.x, ty = threadIdx.y;   // 32 x 8
    int bid = blockIdx.x;
    if (bid < PREP_TD_) {
        const int k0 = (bid % 24) * 32, n0 = (bid / 24) * 32;
#pragma unroll
        for (int j = 0; j < 32; j += 8)
            s[ty + j][tx] = dense_w[(size_t)(k0 + ty + j) * H_ + n0 + tx];
        __syncthreads();
#pragma unroll
        for (int j = 0; j < 32; j += 8)
            Wd[(size_t)(n0 + ty + j) * H_ + k0 + tx] = __float2bfloat16_rn(s[tx][ty + j]);
    } else if (bid < PREP_TD_ + PREP_TP_) {
        bid -= PREP_TD_;
        const int k0 = (bid % 72) * 32, n0 = (bid / 72) * 32;
#pragma unroll
        for (int j = 0; j < 32; j += 8) {
            const int k = k0 + ty + j, n = n0 + tx;
            float v = 0.f;
            if (n < NL_)            v = cls_w[(size_t)k * NL_ + n];
            else if (n < NL_ + DS_) v = fc_w[(size_t)k * DS_ + (n - NL_)];
            s[ty + j][tx] = v;
        }
        __syncthreads();
#pragma unroll
        for (int j = 0; j < 32; j += 8)
            Wp[(size_t)(n0 + ty + j) * H3_ + k0 + tx] = __float2bfloat16_rn(s[tx][ty + j]);
    } else {
        bid -= PREP_TD_ + PREP_TP_;
        const int tid = ty * 32 + tx;
        const int i = bid * 256 + tid;            // pair index, 98304 total over 384 blocks
        if (i < B_ * DS_ / 2) {
            float2 v = ((const float2*)rdesc)[i];
            ((__nv_bfloat162*)rdescb)[i] = __floats2bfloat162_rn(v.x, v.y);
        }
        if (i < NP2_)
            biasP[i] = (i < NL_) ? cls_b[i] : ((i < NL_ + DS_) ? fc_b[i - NL_] : 0.f);
    }
}

// ---------------- post: roleBase+blockIdx.y selects work ----------------
// role 0: P1 reduce + relb + rel-norm + CE ; 1: rdesc norm ; 2/3: z norms from Db
__global__ void post_kernel(const float* __restrict__ P1, const float* __restrict__ biasP,
                            const float* __restrict__ rdesc, const __nv_bfloat16* __restrict__ Db,
                            const int* __restrict__ lab,
                            __nv_bfloat16* __restrict__ relb,
                            float* __restrict__ norms, float* __restrict__ ce, int roleBase)
{
    const int b = blockIdx.x, which = roleBase + blockIdx.y, tid = threadIdx.x;
    __shared__ float red[256];
    __shared__ float vals[NP2_];

    if (which == 0) {
        const int total = B_ * NP2_;
        for (int c = tid; c < NP2_; c += 256) {
            float s = biasP[c];
            int idx = b * NP2_ + c;
#pragma unroll
            for (int z = 0; z < 6; z++) s += P1[(size_t)z * total + idx];
            vals[c] = s;
            if (c >= NL_ && c < NL_ + DS_)
                relb[(size_t)b * DS_ + (c - NL_)] = __float2bfloat16_rn(s);
        }
        __syncthreads();
        float s = 0.f;
        for (int c = NL_ + tid; c < NL_ + DS_; c += 256) { float v = vals[c]; s += v * v; }
        red[tid] = s; __syncthreads();
        for (int st = 128; st > 0; st >>= 1) {
            if (tid < st) red[tid] += red[tid + st];
            __syncthreads();
        }
        if (tid == 0) {
            norms[b] = 1.f / fmaxf(sqrtf(red[0]), EPS_);
            float mx = -INFINITY;
            for (int j = 0; j < NL_; j++) mx = fmaxf(mx, vals[j]);
            float se = 0.f;
            for (int j = 0; j < NL_; j++) se += expf(vals[j] - mx);
            ce[b] = mx + logf(se) - vals[lab[b]];
        }
        return;
    }

    float s = 0.f;
    if (which == 1) {
        const float* x = rdesc + (size_t)b * DS_;
        for (int i = tid; i < DS_; i += 256) { float v = x[i]; s += v * v; }
    } else {
        const __nv_bfloat162* x = (const __nv_bfloat162*)
            (Db + (size_t)b * 4 * H_ + (which == 3 ? 2 * H_ : 0));
        for (int i = tid; i < H_; i += 256) {
            float2 v = __bfloat1622float2(x[i]);
            s += v.x * v.x + v.y * v.y;
        }
    }
    red[tid] = s; __syncthreads();
    for (int st = 128; st > 0; st >>= 1) {
        if (tid < st) red[tid] += red[tid + st];
        __syncthreads();
    }
    if (tid == 0) norms[which * B_ + b] = 1.f / fmaxf(sqrtf(red[0]), EPS_);
}

// ---------------- fused margin on P2 partials ----------------
__global__ void margin_fused(const float* __restrict__ P2, const float* __restrict__ norms,
                             const int* __restrict__ lab, float* __restrict__ mout)
{
    const int b = blockIdx.x, tid = threadIdx.x;
    __shared__ float vals[B_];
    __shared__ float red[256];
    const float rsA = norms[b];
    for (int j = tid; j < B_; j += 256) {
        float s = 0.f;
        const int idx = b * B_ + j;
#pragma unroll
        for (int z = 0; z < 6; z++) s += P2[(size_t)z * B_ * B_ + idx];
        vals[j] = s * rsA * norms[B_ + j];
    }
    __syncthreads();
    const int lb = lab[b];
    float mx = -INFINITY;
    for (int j = tid; j < B_; j += 256)
        if (lab[j] != lb) mx = fmaxf(mx, vals[j]);
    red[tid] = mx; __syncthreads();
    for (int st = 128; st > 0; st >>= 1) {
        if (tid < st) red[tid] = fmaxf(red[tid], red[tid + st]);
        __syncthreads();
    }
    if (tid == 0) {
        float neg = fmaxf(red[0], 0.f);
        mout[b] = fmaxf(neg - vals[b] + GAMMA_, 0.f) * (1.0f - ALPHA_);
    }
}

// ---------------- fused cl on P3 partials ----------------
__global__ void cl_fused(const float* __restrict__ P3, const float* __restrict__ norms,
                         float* __restrict__ cl)
{
    const int b = blockIdx.x, tid = threadIdx.x;
    __shared__ float vals[B_];
    __shared__ float red[256];
    const float rsA = norms[2 * B_ + b] * TEMP_INV_;
    for (int j = tid; j < B_; j += 256) {
        float s = 0.f;
        const int idx = b * B_ + j;
#pragma unroll
        for (int z = 0; z < 6; z++) s += P3[(size_t)z * B_ * B_ + idx];
        vals[j] = s * rsA * norms[3 * B_ + j];
    }
    __syncthreads();
    float mx = -INFINITY;
    for (int j = tid; j < B_; j += 256) mx = fmaxf(mx, vals[j]);
    red[tid] = mx; __syncthreads();
    for (int st = 128; st > 0; st >>= 1) {
        if (tid < st) red[tid] = fmaxf(red[tid], red[tid + st]);
        __syncthreads();
    }
    float m = red[0]; __syncthreads();
    float s = 0.f;
    for (int j = tid; j < B_; j += 256) s += expf(vals[j] - m);
    red[tid] = s; __syncthreads();
    for (int st = 128; st > 0; st >>= 1) {
        if (tid < st) red[tid] += red[tid + st];
        __syncthreads();
    }
    if (tid == 0) cl[b] = m + logf(red[0]) - vals[b];
}

// ---------------- final combine ----------------
__global__ void final_kernel(const float* __restrict__ ce, const float* __restrict__ m,
                             const float* __restrict__ cl, float* __restrict__ out)
{
    int tid = threadIdx.x;
    float v = ce[tid] * (1.0f / B_) + m[tid] + (ALPHA_ / B_) * cl[tid];
    __shared__ float red[512];
    red[tid] = v; __syncthreads();
    for (int st = 256; st > 0; st >>= 1) {
        if (tid < st) red[tid] += red[tid + st];
        __syncthreads();
    }
    if (tid == 0) out[0] = red[0];
}

// ---------------- host launcher (dual-stream fork/join, graph-capturable) ----------------
extern "C" void kernel_launch(void* const* d_in, const int* in_sizes, int n_in,
                              void* d_out, int out_size)
{
    const float* bert    = (const float*)d_in[0];
    const float* rdesc   = (const float*)d_in[1];
    const float* dense_w = (const float*)d_in[2];
    const float* dense_b = (const float*)d_in[3];
    const float* cls_w   = (const float*)d_in[4];
    const float* cls_b   = (const float*)d_in[5];
    const float* fc_w    = (const float*)d_in[6];
    const float* fc_b    = (const float*)d_in[7];
    const int*   eidx    = (const int*)d_in[8];
    const int*   lab     = (const int*)d_in[9];
    float* out = (float*)d_out;

    __nv_bfloat16 *RHb,*TOKSb,*Wd,*Wp,*rdescb,*relb,*Db;
    float *biasP,*P1,*P2,*P3,*norms,*ce,*mm,*cl;
    cudaGetSymbolAddress((void**)&RHb,    g_RHb);
    cudaGetSymbolAddress((void**)&TOKSb,  g_TOKSb);
    cudaGetSymbolAddress((void**)&Wd,     g_Wd);
    cudaGetSymbolAddress((void**)&Wp,     g_Wp);
    cudaGetSymbolAddress((void**)&rdescb, g_rdescb);
    cudaGetSymbolAddress((void**)&relb,   g_relb);
    cudaGetSymbolAddress((void**)&Db,     g_Db);
    cudaGetSymbolAddress((void**)&biasP,  g_biasP);
    cudaGetSymbolAddress((void**)&P1,     g_P1);
    cudaGetSymbolAddress((void**)&P2,     g_P2);
    cudaGetSymbolAddress((void**)&P3,     g_P3);
    cudaGetSymbolAddress((void**)&norms,  g_norms);
    cudaGetSymbolAddress((void**)&ce,     g_ce);
    cudaGetSymbolAddress((void**)&mm,     g_m);
    cudaGetSymbolAddress((void**)&cl,     g_cl);

    static cudaStream_t s1 = nullptr;
    static cudaEvent_t eFork, eG, ePrep, eM;
    if (!s1) {
        cudaStreamCreateWithFlags(&s1, cudaStreamNonBlocking);
        cudaEventCreateWithFlags(&eFork, cudaEventDisableTiming);
        cudaEventCreateWithFlags(&eG,    cudaEventDisableTiming);
        cudaEventCreateWithFlags(&ePrep, cudaEventDisableTiming);
        cudaEventCreateWithFlags(&eM,    cudaEventDisableTiming);
        cudaFuncSetAttribute(mma_nt<0>, cudaFuncAttributeMaxDynamicSharedMemorySize, DYN_SMEM_BYTES_);
        cudaFuncSetAttribute(mma_nt<1>, cudaFuncAttributeMaxDynamicSharedMemorySize, DYN_SMEM_BYTES_);
    }

    // fork s1 from the captured (legacy) stream
    cudaEventRecord(eFork, 0);
    cudaStreamWaitEvent(s1, eFork, 0);

    // stream 0 (chain B): gather -> dense -> z-norms -> cos -> cl
    gather_kernel<<<B_, 192>>>(bert, eidx, RHb, TOKSb);
    cudaEventRecord(eG, 0);

    // stream 1 (chain A): prep -> (after gather) packed -> postA -> C -> margin
    prep_kernel<<<PREP_BLOCKS_, dim3(32, 8), 0, s1>>>(dense_w, cls_w, fc_w, cls_b, fc_b,
                                                      rdesc, Wd, Wp, rdescb, biasP);
    cudaEventRecord(ePrep, s1);

    // dense on stream 0 needs Wd from prep
    cudaStreamWaitEvent(0, ePrep, 0);
    mma_nt<1><<<dim3(12, 16, 1), 256, DYN_SMEM_BYTES_>>>(TOKSb, Wd, nullptr, dense_b, Db,
        4*B_, H_, H_, H_, H_, H_, H_);
    post_kernel<<<dim3(B_, 2), 256>>>(P1, biasP, rdesc, Db, lab, relb, norms, ce, 2); // z-norms
    mma_nt<0><<<dim3(8, 4, 6), 256, DYN_SMEM_BYTES_>>>(Db, Db + 2*H_, P3, nullptr, nullptr,
        B_, B_, 2*H_, 4*H_, 4*H_, B_, 256);
    cl_fused<<<B_, 256>>>(P3, norms, cl);

    // chain A continues on s1 after gather (needs RHb)
    cudaStreamWaitEvent(s1, eG, 0);
    mma_nt<0><<<dim3(7, 4, 6), 256, DYN_SMEM_BYTES_, s1>>>(RHb, Wp, P1, nullptr, nullptr,
        B_, NP2_, H3_, H3_, H3_, NP2_, 384);
    post_kernel<<<dim3(B_, 2), 256, 0, s1>>>(P1, biasP, rdesc, Db, lab, relb, norms, ce, 0);
    mma_nt<0><<<dim3(8, 4, 6), 256, DYN_SMEM_BYTES_, s1>>>(relb, rdescb, P2, nullptr, nullptr,
        B_, B_, DS_, DS_, DS_, B_, 64);
    margin_fused<<<B_, 256, 0, s1>>>(P2, norms, lab, mm);
    cudaEventRecord(eM, s1);

    // join and finish on stream 0
    cudaStreamWaitEvent(0, eM, 0);
    final_kernel<<<1, 512>>>(ce, mm, cl, out);
}

// round 16
// speedup vs baseline: 1.3777x; 1.0406x over previous
#include <cuda_runtime.h>
#include <cuda_bf16.h>
#include <math.h>
#include <stdint.h>

#define B_    512
#define S_    128
#define H_    768
#define DS_   384
#define NL_   40
#define H3_   2304
#define NP2_  448          // packed N padded to 7*64
#define TEMP_INV_ 20.0f
#define ALPHA_    0.15f
#define GAMMA_    7.5f
#define EPS_      1e-8f

// ---------------- scratch ----------------
__device__ __nv_bfloat16 g_RHb[B_ * H3_];
__device__ __nv_bfloat16 g_TOKSb[B_ * 4 * H_];
__device__ __nv_bfloat16 g_Wd[H_ * H_];          // dense_w^T bf16 [N,K]
__device__ __nv_bfloat16 g_Wp[NP2_ * H3_];       // packed W^T bf16 [448,2304]
__device__ __nv_bfloat16 g_rdescb[B_ * DS_];
__device__ __nv_bfloat16 g_relb[B_ * DS_];
__device__ __nv_bfloat16 g_Db[B_ * 4 * H_];
__device__ float g_biasP[NP2_];
__device__ float g_P1[5 * B_ * NP2_];
__device__ float g_P2[3 * B_ * B_];
__device__ float g_P3[4 * B_ * B_];
__device__ float g_norms[4 * B_];
__device__ float g_ce[B_];
__device__ float g_m[B_];
__device__ float g_cl[B_];

__device__ __forceinline__ uint32_t smem_u32(const void* p) {
    uint32_t a;
    asm("{ .reg .u64 t; cvta.to.shared.u64 t, %1; cvt.u32.u64 %0, t; }" : "=r"(a) : "l"(p));
    return a;
}

// ================= mma.sync bf16 NT GEMM, 2-stage cp.async =================
// D tile 128x64 = A[M,K](bf16 rm, lda) @ B[N,K]^T (bf16 rm, ldb)
// K chunk [z*kChunk, min(K, (z+1)*kChunk)) — uneven final chunk allowed (mult of 64).
// MODE 0: raw fp32 -> C + z*M*ldc ; MODE 1: tanh(acc+bias) -> Obf bf16 only
#define KT_ 64
#define SPAD_ 72
#define STAGE_ELEMS_ ((128 + 64) * SPAD_)
#define NSTAGE_ 2
#define DYN_SMEM_BYTES_ (NSTAGE_ * STAGE_ELEMS_ * 2)

template<int MODE>
__global__ __launch_bounds__(256, 2)
void mma_nt(const __nv_bfloat16* __restrict__ A, const __nv_bfloat16* __restrict__ B,
            float* __restrict__ C, const float* __restrict__ bias,
            __nv_bfloat16* __restrict__ Obf,
            int M, int N, int K, int lda, int ldb, int ldc, int kChunk)
{
    extern __shared__ __nv_bfloat16 dyn[];

    const int tid  = threadIdx.x;
    const int warp = tid >> 5, lane = tid & 31;
    const int wm = warp >> 1, wn = warp & 1;
    const int bm = blockIdx.y * 128, bn = blockIdx.x * 64;
    const int kBeg = blockIdx.z * kChunk;

    const int arow = tid >> 1, ac0 = (tid & 1) * 32;
    const __nv_bfloat16* Ag = A + (size_t)(bm + arow) * lda + ac0;
    const int brow = tid >> 2, bc0 = (tid & 3) * 16;
    const __nv_bfloat16* Bg = B + (size_t)(bn + brow) * ldb + bc0;

    const int alr = lane & 15, alc = (lane >> 4) << 3;
    const int blr = lane & 7,  blc = ((lane >> 3) & 1) << 3;

    float acc[2][4][4];
#pragma unroll
    for (int mi = 0; mi < 2; mi++)
#pragma unroll
        for (int ni = 0; ni < 4; ni++)
#pragma unroll
            for (int r = 0; r < 4; r++) acc[mi][ni][r] = 0.f;

    const int kLen = (K - kBeg < kChunk) ? (K - kBeg) : kChunk;
    const int nTiles = kLen / KT_;

    auto stage = [&](int t) {
        __nv_bfloat16* buf = dyn + (t & 1) * STAGE_ELEMS_;
        const int k0 = kBeg + t * KT_;
        uint32_t sa = smem_u32(buf + arow * SPAD_ + ac0);
        const __nv_bfloat16* ag = Ag + k0;
#pragma unroll
        for (int j = 0; j < 4; j++)
            asm volatile("cp.async.cg.shared.global [%0], [%1], 16;"
                         :: "r"(sa + j * 16), "l"(ag + j * 8) : "memory");
        uint32_t sb = smem_u32(buf + 128 * SPAD_ + brow * SPAD_ + bc0);
        const __nv_bfloat16* bg = Bg + k0;
#pragma unroll
        for (int j = 0; j < 2; j++)
            asm volatile("cp.async.cg.shared.global [%0], [%1], 16;"
                         :: "r"(sb + j * 16), "l"(bg + j * 8) : "memory");
        asm volatile("cp.async.commit_group;" ::: "memory");
    };

    stage(0);
    if (nTiles > 1) stage(1);

    for (int t = 0; t < nTiles; t++) {
        if (nTiles - 1 - t >= 1) asm volatile("cp.async.wait_group 1;" ::: "memory");
        else                     asm volatile("cp.async.wait_group 0;" ::: "memory");
        __syncthreads();

        const __nv_bfloat16* cA = dyn + (t & 1) * STAGE_ELEMS_;
        const __nv_bfloat16* cB = cA + 128 * SPAD_;
#pragma unroll
        for (int ks = 0; ks < KT_ / 16; ks++) {
            const int kk = ks * 16;
            uint32_t a[2][4], b[4][2];
#pragma unroll
            for (int mi = 0; mi < 2; mi++) {
                uint32_t addr = smem_u32(cA + (wm * 32 + mi * 16 + alr) * SPAD_ + kk + alc);
                asm volatile("ldmatrix.sync.aligned.m8n8.x4.shared.b16 {%0,%1,%2,%3}, [%4];"
                             : "=r"(a[mi][0]), "=r"(a[mi][1]), "=r"(a[mi][2]), "=r"(a[mi][3])
                             : "r"(addr));
            }
#pragma unroll
            for (int ni = 0; ni < 4; ni++) {
                uint32_t addr = smem_u32(cB + (wn * 32 + ni * 8 + blr) * SPAD_ + kk + blc);
                asm volatile("ldmatrix.sync.aligned.m8n8.x2.shared.b16 {%0,%1}, [%2];"
                             : "=r"(b[ni][0]), "=r"(b[ni][1]) : "r"(addr));
            }
#pragma unroll
            for (int mi = 0; mi < 2; mi++)
#pragma unroll
                for (int ni = 0; ni < 4; ni++) {
                    asm volatile(
                        "mma.sync.aligned.m16n8k16.row.col.f32.bf16.bf16.f32 "
                        "{%0,%1,%2,%3}, {%4,%5,%6,%7}, {%8,%9}, {%0,%1,%2,%3};"
                        : "+f"(acc[mi][ni][0]), "+f"(acc[mi][ni][1]),
                          "+f"(acc[mi][ni][2]), "+f"(acc[mi][ni][3])
                        : "r"(a[mi][0]), "r"(a[mi][1]), "r"(a[mi][2]), "r"(a[mi][3]),
                          "r"(b[ni][0]), "r"(b[ni][1]));
                }
        }

        if (t + 2 < nTiles) {
            __syncthreads();
            stage(t + 2);
        }
    }

    const int g = lane >> 2, cpair = (lane & 3) * 2;
#pragma unroll
    for (int mi = 0; mi < 2; mi++) {
#pragma unroll
        for (int half = 0; half < 2; half++) {
            const int row = bm + wm * 32 + mi * 16 + g + half * 8;
#pragma unroll
            for (int ni = 0; ni < 4; ni++) {
                const int col = bn + wn * 32 + ni * 8 + cpair;
                float v0 = acc[mi][ni][half * 2 + 0];
                float v1 = acc[mi][ni][half * 2 + 1];
                if (MODE == 0) {
                    float* Co = C + (size_t)blockIdx.z * M * ldc + (size_t)row * ldc + col;
                    Co[0] = v0; Co[1] = v1;
                } else {
                    float t0 = tanhf(v0 + bias[col]);
                    float t1 = tanhf(v1 + bias[col + 1]);
                    *(__nv_bfloat162*)(Obf + (size_t)row * ldc + col) =
                        __floats2bfloat162_rn(t0, t1);
                }
            }
        }
    }
}

// ---------------- gather + tanh -> bf16 ----------------
__global__ void gather_kernel(const float* __restrict__ bert,
                              const int* __restrict__ eidx,
                              __nv_bfloat16* __restrict__ RHb,
                              __nv_bfloat16* __restrict__ TOKSb)
{
    int b = blockIdx.x, t = threadIdx.x;  // 0..191
    const float* base0 = bert + (size_t)b * 2 * S_ * H_;
    const float* base1 = base0 + S_ * H_;
    int i0 = eidx[b*4+0], i1 = eidx[b*4+1], i2 = eidx[b*4+2], i3 = eidx[b*4+3];
    float4 c  = ((const float4*)base0)[t];
    float4 hh = ((const float4*)(base0 + (size_t)i0*H_))[t];
    float4 tl = ((const float4*)(base0 + (size_t)i1*H_))[t];
    float4 a2 = ((const float4*)(base1 + (size_t)i2*H_))[t];
    float4 b2 = ((const float4*)(base1 + (size_t)i3*H_))[t];

    __nv_bfloat162* rh = (__nv_bfloat162*)(RHb + (size_t)b * H3_);
    __nv_bfloat162* tk = (__nv_bfloat162*)(TOKSb + (size_t)b * 4 * H_);
    rh[2*t]       = __floats2bfloat162_rn(tanhf(c.x),  tanhf(c.y));
    rh[2*t+1]     = __floats2bfloat162_rn(tanhf(c.z),  tanhf(c.w));
    rh[384+2*t]   = __floats2bfloat162_rn(tanhf(hh.x), tanhf(hh.y));
    rh[384+2*t+1] = __floats2bfloat162_rn(tanhf(hh.z), tanhf(hh.w));
    rh[768+2*t]   = __floats2bfloat162_rn(tanhf(tl.x), tanhf(tl.y));
    rh[768+2*t+1] = __floats2bfloat162_rn(tanhf(tl.z), tanhf(tl.w));
    tk[2*t]        = __floats2bfloat162_rn(hh.x, hh.y);
    tk[2*t+1]      = __floats2bfloat162_rn(hh.z, hh.w);
    tk[384+2*t]    = __floats2bfloat162_rn(tl.x, tl.y);
    tk[384+2*t+1]  = __floats2bfloat162_rn(tl.z, tl.w);
    tk[768+2*t]    = __floats2bfloat162_rn(a2.x, a2.y);
    tk[768+2*t+1]  = __floats2bfloat162_rn(a2.z, a2.w);
    tk[1152+2*t]   = __floats2bfloat162_rn(b2.x, b2.y);
    tk[1152+2*t+1] = __floats2bfloat162_rn(b2.z, b2.w);
}

// ---------------- fused prep: weight transposes + rdesc convert + bias pack ----------------
#define PREP_TD_ 576
#define PREP_TP_ 1008
#define PREP_MISC_ 384
#define PREP_BLOCKS_ (PREP_TD_ + PREP_TP_ + PREP_MISC_)
__global__ void prep_kernel(const float* __restrict__ dense_w,
                            const float* __restrict__ cls_w, const float* __restrict__ fc_w,
                            const float* __restrict__ cls_b, const float* __restrict__ fc_b,
                            const float* __restrict__ rdesc,
                            __nv_bfloat16* __restrict__ Wd, __nv_bfloat16* __restrict__ Wp,
                            __nv_bfloat16* __restrict__ rdescb, float* __restrict__ biasP)
{
    __shared__ float s[32][33];
    const int tx = threadIdx.x, ty = threadIdx.y;   // 32 x 8
    int bid = blockIdx.x;
    if (bid < PREP_TD_) {
        const int k0 = (bid % 24) * 32, n0 = (bid / 24) * 32;
#pragma unroll
        for (int j = 0; j < 32; j += 8)
            s[ty + j][tx] = dense_w[(size_t)(k0 + ty + j) * H_ + n0 + tx];
        __syncthreads();
#pragma unroll
        for (int j = 0; j < 32; j += 8)
            Wd[(size_t)(n0 + ty + j) * H_ + k0 + tx] = __float2bfloat16_rn(s[tx][ty + j]);
    } else if (bid < PREP_TD_ + PREP_TP_) {
        bid -= PREP_TD_;
        const int k0 = (bid % 72) * 32, n0 = (bid / 72) * 32;
#pragma unroll
        for (int j = 0; j < 32; j += 8) {
            const int k = k0 + ty + j, n = n0 + tx;
            float v = 0.f;
            if (n < NL_)            v = cls_w[(size_t)k * NL_ + n];
            else if (n < NL_ + DS_) v = fc_w[(size_t)k * DS_ + (n - NL_)];
            s[ty + j][tx] = v;
        }
        __syncthreads();
#pragma unroll
        for (int j = 0; j < 32; j += 8)
            Wp[(size_t)(n0 + ty + j) * H3_ + k0 + tx] = __float2bfloat16_rn(s[tx][ty + j]);
    } else {
        bid -= PREP_TD_ + PREP_TP_;
        const int tid = ty * 32 + tx;
        const int i = bid * 256 + tid;            // pair index, 98304 total / 384 blocks
        if (i < B_ * DS_ / 2) {
            float2 v = ((const float2*)rdesc)[i];
            ((__nv_bfloat162*)rdescb)[i] = __floats2bfloat162_rn(v.x, v.y);
        }
        if (i < NP2_)
            biasP[i] = (i < NL_) ? cls_b[i] : ((i < NL_ + DS_) ? fc_b[i - NL_] : 0.f);
    }
}

// ---------------- post: roleBase+blockIdx.y selects work ----------------
__global__ void post_kernel(const float* __restrict__ P1, const float* __restrict__ biasP,
                            const float* __restrict__ rdesc, const __nv_bfloat16* __restrict__ Db,
                            const int* __restrict__ lab,
                            __nv_bfloat16* __restrict__ relb,
                            float* __restrict__ norms, float* __restrict__ ce,
                            int roleBase, int nsplit)
{
    const int b = blockIdx.x, which = roleBase + blockIdx.y, tid = threadIdx.x;
    __shared__ float red[256];
    __shared__ float vals[NP2_];

    if (which == 0) {
        const int total = B_ * NP2_;
        for (int c = tid; c < NP2_; c += 256) {
            float s = biasP[c];
            int idx = b * NP2_ + c;
            for (int z = 0; z < nsplit; z++) s += P1[(size_t)z * total + idx];
            vals[c] = s;
            if (c >= NL_ && c < NL_ + DS_)
                relb[(size_t)b * DS_ + (c - NL_)] = __float2bfloat16_rn(s);
        }
        __syncthreads();
        float s = 0.f;
        for (int c = NL_ + tid; c < NL_ + DS_; c += 256) { float v = vals[c]; s += v * v; }
        red[tid] = s; __syncthreads();
        for (int st = 128; st > 0; st >>= 1) {
            if (tid < st) red[tid] += red[tid + st];
            __syncthreads();
        }
        if (tid == 0) {
            norms[b] = 1.f / fmaxf(sqrtf(red[0]), EPS_);
            float mx = -INFINITY;
            for (int j = 0; j < NL_; j++) mx = fmaxf(mx, vals[j]);
            float se = 0.f;
            for (int j = 0; j < NL_; j++) se += expf(vals[j] - mx);
            ce[b] = mx + logf(se) - vals[lab[b]];
        }
        return;
    }

    float s = 0.f;
    if (which == 1) {
        const float* x = rdesc + (size_t)b * DS_;
        for (int i = tid; i < DS_; i += 256) { float v = x[i]; s += v * v; }
    } else {
        const __nv_bfloat162* x = (const __nv_bfloat162*)
            (Db + (size_t)b * 4 * H_ + (which == 3 ? 2 * H_ : 0));
        for (int i = tid; i < H_; i += 256) {
            float2 v = __bfloat1622float2(x[i]);
            s += v.x * v.x + v.y * v.y;
        }
    }
    red[tid] = s; __syncthreads();
    for (int st = 128; st > 0; st >>= 1) {
        if (tid < st) red[tid] += red[tid + st];
        __syncthreads();
    }
    if (tid == 0) norms[which * B_ + b] = 1.f / fmaxf(sqrtf(red[0]), EPS_);
}

// ---------------- fused margin on P2 partials ----------------
__global__ void margin_fused(const float* __restrict__ P2, const float* __restrict__ norms,
                             const int* __restrict__ lab, float* __restrict__ mout, int nsplit)
{
    const int b = blockIdx.x, tid = threadIdx.x;
    __shared__ float vals[B_];
    __shared__ float red[256];
    const float rsA = norms[b];
    for (int j = tid; j < B_; j += 256) {
        float s = 0.f;
        const int idx = b * B_ + j;
        for (int z = 0; z < nsplit; z++) s += P2[(size_t)z * B_ * B_ + idx];
        vals[j] = s * rsA * norms[B_ + j];
    }
    __syncthreads();
    const int lb = lab[b];
    float mx = -INFINITY;
    for (int j = tid; j < B_; j += 256)
        if (lab[j] != lb) mx = fmaxf(mx, vals[j]);
    red[tid] = mx; __syncthreads();
    for (int st = 128; st > 0; st >>= 1) {
        if (tid < st) red[tid] = fmaxf(red[tid], red[tid + st]);
        __syncthreads();
    }
    if (tid == 0) {
        float neg = fmaxf(red[0], 0.f);
        mout[b] = fmaxf(neg - vals[b] + GAMMA_, 0.f) * (1.0f - ALPHA_);
    }
}

// ---------------- fused cl on P3 partials ----------------
__global__ void cl_fused(const float* __restrict__ P3, const float* __restrict__ norms,
                         float* __restrict__ cl, int nsplit)
{
    const int b = blockIdx.x, tid = threadIdx.x;
    __shared__ float vals[B_];
    __shared__ float red[256];
    const float rsA = norms[2 * B_ + b] * TEMP_INV_;
    for (int j = tid; j < B_; j += 256) {
        float s = 0.f;
        const int idx = b * B_ + j;
        for (int z = 0; z < nsplit; z++) s += P3[(size_t)z * B_ * B_ + idx];
        vals[j] = s * rsA * norms[3 * B_ + j];
    }
    __syncthreads();
    float mx = -INFINITY;
    for (int j = tid; j < B_; j += 256) mx = fmaxf(mx, vals[j]);
    red[tid] = mx; __syncthreads();
    for (int st = 128; st > 0; st >>= 1) {
        if (tid < st) red[tid] = fmaxf(red[tid], red[tid + st]);
        __syncthreads();
    }
    float m = red[0]; __syncthreads();
    float s = 0.f;
    for (int j = tid; j < B_; j += 256) s += expf(vals[j] - m);
    red[tid] = s; __syncthreads();
    for (int st = 128; st > 0; st >>= 1) {
        if (tid < st) red[tid] += red[tid + st];
        __syncthreads();
    }
    if (tid == 0) cl[b] = m + logf(red[0]) - vals[b];
}

// ---------------- final combine ----------------
__global__ void final_kernel(const float* __restrict__ ce, const float* __restrict__ m,
                             const float* __restrict__ cl, float* __restrict__ out)
{
    int tid = threadIdx.x;
    float v = ce[tid] * (1.0f / B_) + m[tid] + (ALPHA_ / B_) * cl[tid];
    __shared__ float red[512];
    red[tid] = v; __syncthreads();
    for (int st = 256; st > 0; st >>= 1) {
        if (tid < st) red[tid] += red[tid + st];
        __syncthreads();
    }
    if (tid == 0) out[0] = red[0];
}

// ---------------- host launcher (3-stream fork/join, graph-capturable) ----------------
extern "C" void kernel_launch(void* const* d_in, const int* in_sizes, int n_in,
                              void* d_out, int out_size)
{
    const float* bert    = (const float*)d_in[0];
    const float* rdesc   = (const float*)d_in[1];
    const float* dense_w = (const float*)d_in[2];
    const float* dense_b = (const float*)d_in[3];
    const float* cls_w   = (const float*)d_in[4];
    const float* cls_b   = (const float*)d_in[5];
    const float* fc_w    = (const float*)d_in[6];
    const float* fc_b    = (const float*)d_in[7];
    const int*   eidx    = (const int*)d_in[8];
    const int*   lab     = (const int*)d_in[9];
    float* out = (float*)d_out;

    __nv_bfloat16 *RHb,*TOKSb,*Wd,*Wp,*rdescb,*relb,*Db;
    float *biasP,*P1,*P2,*P3,*norms,*ce,*mm,*cl;
    cudaGetSymbolAddress((void**)&RHb,    g_RHb);
    cudaGetSymbolAddress((void**)&TOKSb,  g_TOKSb);
    cudaGetSymbolAddress((void**)&Wd,     g_Wd);
    cudaGetSymbolAddress((void**)&Wp,     g_Wp);
    cudaGetSymbolAddress((void**)&rdescb, g_rdescb);
    cudaGetSymbolAddress((void**)&relb,   g_relb);
    cudaGetSymbolAddress((void**)&Db,     g_Db);
    cudaGetSymbolAddress((void**)&biasP,  g_biasP);
    cudaGetSymbolAddress((void**)&P1,     g_P1);
    cudaGetSymbolAddress((void**)&P2,     g_P2);
    cudaGetSymbolAddress((void**)&P3,     g_P3);
    cudaGetSymbolAddress((void**)&norms,  g_norms);
    cudaGetSymbolAddress((void**)&ce,     g_ce);
    cudaGetSymbolAddress((void**)&mm,     g_m);
    cudaGetSymbolAddress((void**)&cl,     g_cl);

    static cudaStream_t s1 = nullptr, s2 = nullptr;
    static cudaEvent_t eFork, eG, ePrep, eM, eD, eZ;
    if (!s1) {
        cudaStreamCreateWithFlags(&s1, cudaStreamNonBlocking);
        cudaStreamCreateWithFlags(&s2, cudaStreamNonBlocking);
        cudaEventCreateWithFlags(&eFork, cudaEventDisableTiming);
        cudaEventCreateWithFlags(&eG,    cudaEventDisableTiming);
        cudaEventCreateWithFlags(&ePrep, cudaEventDisableTiming);
        cudaEventCreateWithFlags(&eM,    cudaEventDisableTiming);
        cudaEventCreateWithFlags(&eD,    cudaEventDisableTiming);
        cudaEventCreateWithFlags(&eZ,    cudaEventDisableTiming);
        cudaFuncSetAttribute(mma_nt<0>, cudaFuncAttributeMaxDynamicSharedMemorySize, DYN_SMEM_BYTES_);
        cudaFuncSetAttribute(mma_nt<1>, cudaFuncAttributeMaxDynamicSharedMemorySize, DYN_SMEM_BYTES_);
    }

    // fork s1 from the captured (legacy) stream
    cudaEventRecord(eFork, 0);
    cudaStreamWaitEvent(s1, eFork, 0);

    // stream 0 (chain B): gather -> dense -> cos -> cl
    gather_kernel<<<B_, 192>>>(bert, eidx, RHb, TOKSb);
    cudaEventRecord(eG, 0);

    // stream 1 (chain A): prep -> (after gather) packed -> post0 -> C -> margin
    prep_kernel<<<PREP_BLOCKS_, dim3(32, 8), 0, s1>>>(dense_w, cls_w, fc_w, cls_b, fc_b,
                                                      rdesc, Wd, Wp, rdescb, biasP);
    cudaEventRecord(ePrep, s1);

    // dense on stream 0 needs Wd from prep
    cudaStreamWaitEvent(0, ePrep, 0);
    mma_nt<1><<<dim3(12, 16, 1), 256, DYN_SMEM_BYTES_>>>(TOKSb, Wd, nullptr, dense_b, Db,
        4*B_, H_, H_, H_, H_, H_, H_);
    cudaEventRecord(eD, 0);

    // stream 2: z-norms overlapped with the cos GEMM
    cudaStreamWaitEvent(s2, eD, 0);
    post_kernel<<<dim3(B_, 2), 256, 0, s2>>>(P1, biasP, rdesc, Db, lab, relb, norms, ce, 2, 0);
    cudaEventRecord(eZ, s2);

    // cos (NT): z1 @ z2^T, split-K 4 uneven-free (24 tiles / 4) -> 128 CTAs, one wave
    mma_nt<0><<<dim3(8, 4, 4), 256, DYN_SMEM_BYTES_>>>(Db, Db + 2*H_, P3, nullptr, nullptr,
        B_, B_, 2*H_, 4*H_, 4*H_, B_, 384);
    cudaStreamWaitEvent(0, eZ, 0);
    cl_fused<<<B_, 256>>>(P3, norms, cl, 4);

    // chain A continues on s1 after gather (needs RHb)
    cudaStreamWaitEvent(s1, eG, 0);
    // packed: split-K 5 (chunks of 8 tiles, last chunk 4) -> 140 CTAs, one wave
    mma_nt<0><<<dim3(7, 4, 5), 256, DYN_SMEM_BYTES_, s1>>>(RHb, Wp, P1, nullptr, nullptr,
        B_, NP2_, H3_, H3_, H3_, NP2_, 512);
    post_kernel<<<dim3(B_, 2), 256, 0, s1>>>(P1, biasP, rdesc, Db, lab, relb, norms, ce, 0, 5);
    // C: split-K 3 (2 tiles each) -> 96 CTAs, one wave
    mma_nt<0><<<dim3(8, 4, 3), 256, DYN_SMEM_BYTES_, s1>>>(relb, rdescb, P2, nullptr, nullptr,
        B_, B_, DS_, DS_, DS_, B_, 128);
    margin_fused<<<B_, 256, 0, s1>>>(P2, norms, lab, mm, 3);
    cudaEventRecord(eM, s1);

    // join and finish on stream 0
    cudaStreamWaitEvent(0, eM, 0);
    final_kernel<<<1, 512>>>(ce, mm, cl, out);
}

// round 17
// speedup vs baseline: 1.5306x; 1.1110x over previous
#include <cuda_runtime.h>
#include <cuda_bf16.h>
#include <math.h>
#include <stdint.h>

#define B_    512
#define S_    128
#define H_    768
#define DS_   384
#define NL_   40
#define H3_   2304
#define NP2_  448          // packed N padded to 7*64
#define TEMP_INV_ 20.0f
#define ALPHA_    0.15f
#define GAMMA_    7.5f
#define EPS_      1e-8f

// ---------------- scratch ----------------
__device__ __nv_bfloat16 g_RHb[B_ * H3_];
__device__ __nv_bfloat16 g_TOKSb[B_ * 4 * H_];
__device__ __nv_bfloat16 g_Wd[H_ * H_];          // dense_w^T bf16 [N,K]
__device__ __nv_bfloat16 g_Wp[NP2_ * H3_];       // packed W^T bf16 [448,2304]
__device__ __nv_bfloat16 g_rdescb[B_ * DS_];
__device__ __nv_bfloat16 g_relb[B_ * DS_];
__device__ __nv_bfloat16 g_Db[B_ * 4 * H_];
__device__ float g_biasP[NP2_];
__device__ float g_P1[4 * B_ * NP2_];
__device__ float g_P2[2 * B_ * B_];
__device__ float g_P3[3 * B_ * B_];
__device__ float g_norms[4 * B_];
__device__ float g_ce[B_];
__device__ float g_m[B_];
__device__ float g_cl[B_];

__device__ __forceinline__ uint32_t smem_u32(const void* p) {
    uint32_t a;
    asm("{ .reg .u64 t; cvta.to.shared.u64 t, %1; cvt.u32.u64 %0, t; }" : "=r"(a) : "l"(p));
    return a;
}

// ================= mma.sync bf16 NT GEMM, 2-stage cp.async (unchanged core) =================
#define KT_ 64
#define SPAD_ 72
#define STAGE_ELEMS_ ((128 + 64) * SPAD_)
#define NSTAGE_ 2
#define DYN_SMEM_BYTES_ (NSTAGE_ * STAGE_ELEMS_ * 2)

template<int MODE>
__global__ __launch_bounds__(256, 2)
void mma_nt(const __nv_bfloat16* __restrict__ A, const __nv_bfloat16* __restrict__ B,
            float* __restrict__ C, const float* __restrict__ bias,
            __nv_bfloat16* __restrict__ Obf,
            int M, int N, int K, int lda, int ldb, int ldc, int kChunk)
{
    extern __shared__ __nv_bfloat16 dyn[];

    const int tid  = threadIdx.x;
    const int warp = tid >> 5, lane = tid & 31;
    const int wm = warp >> 1, wn = warp & 1;
    const int bm = blockIdx.y * 128, bn = blockIdx.x * 64;
    const int kBeg = blockIdx.z * kChunk;

    const int arow = tid >> 1, ac0 = (tid & 1) * 32;
    const __nv_bfloat16* Ag = A + (size_t)(bm + arow) * lda + ac0;
    const int brow = tid >> 2, bc0 = (tid & 3) * 16;
    const __nv_bfloat16* Bg = B + (size_t)(bn + brow) * ldb + bc0;

    const int alr = lane & 15, alc = (lane >> 4) << 3;
    const int blr = lane & 7,  blc = ((lane >> 3) & 1) << 3;

    float acc[2][4][4];
#pragma unroll
    for (int mi = 0; mi < 2; mi++)
#pragma unroll
        for (int ni = 0; ni < 4; ni++)
#pragma unroll
            for (int r = 0; r < 4; r++) acc[mi][ni][r] = 0.f;

    const int kLen = (K - kBeg < kChunk) ? (K - kBeg) : kChunk;
    const int nTiles = kLen / KT_;

    auto stage = [&](int t) {
        __nv_bfloat16* buf = dyn + (t & 1) * STAGE_ELEMS_;
        const int k0 = kBeg + t * KT_;
        uint32_t sa = smem_u32(buf + arow * SPAD_ + ac0);
        const __nv_bfloat16* ag = Ag + k0;
#pragma unroll
        for (int j = 0; j < 4; j++)
            asm volatile("cp.async.cg.shared.global [%0], [%1], 16;"
                         :: "r"(sa + j * 16), "l"(ag + j * 8) : "memory");
        uint32_t sb = smem_u32(buf + 128 * SPAD_ + brow * SPAD_ + bc0);
        const __nv_bfloat16* bg = Bg + k0;
#pragma unroll
        for (int j = 0; j < 2; j++)
            asm volatile("cp.async.cg.shared.global [%0], [%1], 16;"
                         :: "r"(sb + j * 16), "l"(bg + j * 8) : "memory");
        asm volatile("cp.async.commit_group;" ::: "memory");
    };

    stage(0);
    if (nTiles > 1) stage(1);

    for (int t = 0; t < nTiles; t++) {
        if (nTiles - 1 - t >= 1) asm volatile("cp.async.wait_group 1;" ::: "memory");
        else                     asm volatile("cp.async.wait_group 0;" ::: "memory");
        __syncthreads();

        const __nv_bfloat16* cA = dyn + (t & 1) * STAGE_ELEMS_;
        const __nv_bfloat16* cB = cA + 128 * SPAD_;
#pragma unroll
        for (int ks = 0; ks < KT_ / 16; ks++) {
            const int kk = ks * 16;
            uint32_t a[2][4], b[4][2];
#pragma unroll
            for (int mi = 0; mi < 2; mi++) {
                uint32_t addr = smem_u32(cA + (wm * 32 + mi * 16 + alr) * SPAD_ + kk + alc);
                asm volatile("ldmatrix.sync.aligned.m8n8.x4.shared.b16 {%0,%1,%2,%3}, [%4];"
                             : "=r"(a[mi][0]), "=r"(a[mi][1]), "=r"(a[mi][2]), "=r"(a[mi][3])
                             : "r"(addr));
            }
#pragma unroll
            for (int ni = 0; ni < 4; ni++) {
                uint32_t addr = smem_u32(cB + (wn * 32 + ni * 8 + blr) * SPAD_ + kk + blc);
                asm volatile("ldmatrix.sync.aligned.m8n8.x2.shared.b16 {%0,%1}, [%2];"
                             : "=r"(b[ni][0]), "=r"(b[ni][1]) : "r"(addr));
            }
#pragma unroll
            for (int mi = 0; mi < 2; mi++)
#pragma unroll
                for (int ni = 0; ni < 4; ni++) {
                    asm volatile(
                        "mma.sync.aligned.m16n8k16.row.col.f32.bf16.bf16.f32 "
                        "{%0,%1,%2,%3}, {%4,%5,%6,%7}, {%8,%9}, {%0,%1,%2,%3};"
                        : "+f"(acc[mi][ni][0]), "+f"(acc[mi][ni][1]),
                          "+f"(acc[mi][ni][2]), "+f"(acc[mi][ni][3])
                        : "r"(a[mi][0]), "r"(a[mi][1]), "r"(a[mi][2]), "r"(a[mi][3]),
                          "r"(b[ni][0]), "r"(b[ni][1]));
                }
        }

        if (t + 2 < nTiles) {
            __syncthreads();
            stage(t + 2);
        }
    }

    const int g = lane >> 2, cpair = (lane & 3) * 2;
#pragma unroll
    for (int mi = 0; mi < 2; mi++) {
#pragma unroll
        for (int half = 0; half < 2; half++) {
            const int row = bm + wm * 32 + mi * 16 + g + half * 8;
#pragma unroll
            for (int ni = 0; ni < 4; ni++) {
                const int col = bn + wn * 32 + ni * 8 + cpair;
                float v0 = acc[mi][ni][half * 2 + 0];
                float v1 = acc[mi][ni][half * 2 + 1];
                if (MODE == 0) {
                    float* Co = C + (size_t)blockIdx.z * M * ldc + (size_t)row * ldc + col;
                    Co[0] = v0; Co[1] = v1;
                } else {
                    float t0 = tanhf(v0 + bias[col]);
                    float t1 = tanhf(v1 + bias[col + 1]);
                    *(__nv_bfloat162*)(Obf + (size_t)row * ldc + col) =
                        __floats2bfloat162_rn(t0, t1);
                }
            }
        }
    }
}

// ---------------- gather + tanh -> bf16 ----------------
__global__ void gather_kernel(const float* __restrict__ bert,
                              const int* __restrict__ eidx,
                              __nv_bfloat16* __restrict__ RHb,
                              __nv_bfloat16* __restrict__ TOKSb)
{
    int b = blockIdx.x, t = threadIdx.x;  // 0..191
    const float* base0 = bert + (size_t)b * 2 * S_ * H_;
    const float* base1 = base0 + S_ * H_;
    int i0 = eidx[b*4+0], i1 = eidx[b*4+1], i2 = eidx[b*4+2], i3 = eidx[b*4+3];
    float4 c  = ((const float4*)base0)[t];
    float4 hh = ((const float4*)(base0 + (size_t)i0*H_))[t];
    float4 tl = ((const float4*)(base0 + (size_t)i1*H_))[t];
    float4 a2 = ((const float4*)(base1 + (size_t)i2*H_))[t];
    float4 b2 = ((const float4*)(base1 + (size_t)i3*H_))[t];

    __nv_bfloat162* rh = (__nv_bfloat162*)(RHb + (size_t)b * H3_);
    __nv_bfloat162* tk = (__nv_bfloat162*)(TOKSb + (size_t)b * 4 * H_);
    rh[2*t]       = __floats2bfloat162_rn(tanhf(c.x),  tanhf(c.y));
    rh[2*t+1]     = __floats2bfloat162_rn(tanhf(c.z),  tanhf(c.w));
    rh[384+2*t]   = __floats2bfloat162_rn(tanhf(hh.x), tanhf(hh.y));
    rh[384+2*t+1] = __floats2bfloat162_rn(tanhf(hh.z), tanhf(hh.w));
    rh[768+2*t]   = __floats2bfloat162_rn(tanhf(tl.x), tanhf(tl.y));
    rh[768+2*t+1] = __floats2bfloat162_rn(tanhf(tl.z), tanhf(tl.w));
    tk[2*t]        = __floats2bfloat162_rn(hh.x, hh.y);
    tk[2*t+1]      = __floats2bfloat162_rn(hh.z, hh.w);
    tk[384+2*t]    = __floats2bfloat162_rn(tl.x, tl.y);
    tk[384+2*t+1]  = __floats2bfloat162_rn(tl.z, tl.w);
    tk[768+2*t]    = __floats2bfloat162_rn(a2.x, a2.y);
    tk[768+2*t+1]  = __floats2bfloat162_rn(a2.z, a2.w);
    tk[1152+2*t]   = __floats2bfloat162_rn(b2.x, b2.y);
    tk[1152+2*t+1] = __floats2bfloat162_rn(b2.z, b2.w);
}

// ---------------- fused prep: weight transposes + rdesc convert + bias pack ----------------
#define PREP_TD_ 576
#define PREP_TP_ 1008
#define PREP_MISC_ 384
#define PREP_BLOCKS_ (PREP_TD_ + PREP_TP_ + PREP_MISC_)
__global__ void prep_kernel(const float* __restrict__ dense_w,
                            const float* __restrict__ cls_w, const float* __restrict__ fc_w,
                            const float* __restrict__ cls_b, const float* __restrict__ fc_b,
                            const float* __restrict__ rdesc,
                            __nv_bfloat16* __restrict__ Wd, __nv_bfloat16* __restrict__ Wp,
                            __nv_bfloat16* __restrict__ rdescb, float* __restrict__ biasP)
{
    __shared__ float s[32][33];
    const int tx = threadIdx.x, ty = threadIdx.y;   // 32 x 8
    int bid = blockIdx.x;
    if (bid < PREP_TD_) {
        const int k0 = (bid % 24) * 32, n0 = (bid / 24) * 32;
#pragma unroll
        for (int j = 0; j < 32; j += 8)
            s[ty + j][tx] = dense_w[(size_t)(k0 + ty + j) * H_ + n0 + tx];
        __syncthreads();
#pragma unroll
        for (int j = 0; j < 32; j += 8)
            Wd[(size_t)(n0 + ty + j) * H_ + k0 + tx] = __float2bfloat16_rn(s[tx][ty + j]);
    } else if (bid < PREP_TD_ + PREP_TP_) {
        bid -= PREP_TD_;
        const int k0 = (bid % 72) * 32, n0 = (bid / 72) * 32;
#pragma unroll
        for (int j = 0; j < 32; j += 8) {
            const int k = k0 + ty + j, n = n0 + tx;
            float v = 0.f;
            if (n < NL_)            v = cls_w[(size_t)k * NL_ + n];
            else if (n < NL_ + DS_) v = fc_w[(size_t)k * DS_ + (n - NL_)];
            s[ty + j][tx] = v;
        }
        __syncthreads();
#pragma unroll
        for (int j = 0; j < 32; j += 8)
            Wp[(size_t)(n0 + ty + j) * H3_ + k0 + tx] = __float2bfloat16_rn(s[tx][ty + j]);
    } else {
        bid -= PREP_TD_ + PREP_TP_;
        const int tid = ty * 32 + tx;
        const int i = bid * 256 + tid;            // pair index, 98304 / 384 blocks
        if (i < B_ * DS_ / 2) {
            float2 v = ((const float2*)rdesc)[i];
            ((__nv_bfloat162*)rdescb)[i] = __floats2bfloat162_rn(v.x, v.y);
        }
        if (i < NP2_)
            biasP[i] = (i < NL_) ? cls_b[i] : ((i < NL_ + DS_) ? fc_b[i - NL_] : 0.f);
    }
}

// ---------------- post: roleBase+blockIdx.y selects work ----------------
// role 0: P1 reduce + relb + rel-norm + CE ; 1: rdesc norm ; 2/3: z norms from Db
__global__ void post_kernel(const float* __restrict__ P1, const float* __restrict__ biasP,
                            const float* __restrict__ rdesc, const __nv_bfloat16* __restrict__ Db,
                            const int* __restrict__ lab,
                            __nv_bfloat16* __restrict__ relb,
                            float* __restrict__ norms, float* __restrict__ ce,
                            int roleBase, int nsplit)
{
    const int b = blockIdx.x, which = roleBase + blockIdx.y, tid = threadIdx.x;
    __shared__ float red[256];
    __shared__ float vals[NP2_];

    if (which == 0) {
        const int total = B_ * NP2_;
        for (int c = tid; c < NP2_; c += 256) {
            float s = biasP[c];
            int idx = b * NP2_ + c;
            for (int z = 0; z < nsplit; z++) s += P1[(size_t)z * total + idx];
            vals[c] = s;
            if (c >= NL_ && c < NL_ + DS_)
                relb[(size_t)b * DS_ + (c - NL_)] = __float2bfloat16_rn(s);
        }
        __syncthreads();
        float s = 0.f;
        for (int c = NL_ + tid; c < NL_ + DS_; c += 256) { float v = vals[c]; s += v * v; }
        red[tid] = s; __syncthreads();
        for (int st = 128; st > 0; st >>= 1) {
            if (tid < st) red[tid] += red[tid + st];
            __syncthreads();
        }
        if (tid == 0) {
            norms[b] = 1.f / fmaxf(sqrtf(red[0]), EPS_);
            float mx = -INFINITY;
            for (int j = 0; j < NL_; j++) mx = fmaxf(mx, vals[j]);
            float se = 0.f;
            for (int j = 0; j < NL_; j++) se += expf(vals[j] - mx);
            ce[b] = mx + logf(se) - vals[lab[b]];
        }
        return;
    }

    float s = 0.f;
    if (which == 1) {
        const float* x = rdesc + (size_t)b * DS_;
        for (int i = tid; i < DS_; i += 256) { float v = x[i]; s += v * v; }
    } else {
        const __nv_bfloat162* x = (const __nv_bfloat162*)
            (Db + (size_t)b * 4 * H_ + (which == 3 ? 2 * H_ : 0));
        for (int i = tid; i < H_; i += 256) {
            float2 v = __bfloat1622float2(x[i]);
            s += v.x * v.x + v.y * v.y;
        }
    }
    red[tid] = s; __syncthreads();
    for (int st = 128; st > 0; st >>= 1) {
        if (tid < st) red[tid] += red[tid + st];
        __syncthreads();
    }
    if (tid == 0) norms[which * B_ + b] = 1.f / fmaxf(sqrtf(red[0]), EPS_);
}

// ---------------- fused margin on P2 partials (512 thr) ----------------
__global__ void margin_fused(const float* __restrict__ P2, const float* __restrict__ norms,
                             const int* __restrict__ lab, float* __restrict__ mout, int nsplit)
{
    const int b = blockIdx.x, tid = threadIdx.x;   // 512 threads
    __shared__ float red[512];
    const float rsA = norms[b];
    float s = 0.f;
    const int idx = b * B_ + tid;
    for (int z = 0; z < nsplit; z++) s += P2[(size_t)z * B_ * B_ + idx];
    const float v = s * rsA * norms[B_ + tid];
    float pos_v = __shfl_sync(0xffffffffu, v, 0);  // placeholder; pos read via smem below
    red[tid] = v; __syncthreads();
    const float pos = red[b & 511];                // vals[b] (b < 512)
    __syncthreads();
    const int lb = lab[b];
    float mx = (lab[tid] != lb) ? v : -INFINITY;
    red[tid] = mx; __syncthreads();
    for (int st = 256; st > 0; st >>= 1) {
        if (tid < st) red[tid] = fmaxf(red[tid], red[tid + st]);
        __syncthreads();
    }
    if (tid == 0) {
        float neg = fmaxf(red[0], 0.f);
        mout[b] = fmaxf(neg - pos + GAMMA_, 0.f) * (1.0f - ALPHA_);
    }
    (void)pos_v;
}

// ---------------- fused cl on P3 partials (512 thr) ----------------
__global__ void cl_fused(const float* __restrict__ P3, const float* __restrict__ norms,
                         float* __restrict__ cl, int nsplit)
{
    const int b = blockIdx.x, tid = threadIdx.x;   // 512 threads
    __shared__ float red[512];
    const float rsA = norms[2 * B_ + b] * TEMP_INV_;
    float s = 0.f;
    const int idx = b * B_ + tid;
    for (int z = 0; z < nsplit; z++) s += P3[(size_t)z * B_ * B_ + idx];
    const float v = s * rsA * norms[3 * B_ + tid];
    red[tid] = v; __syncthreads();
    const float pos = red[b & 511];
    __syncthreads();
    red[tid] = v; __syncthreads();
    for (int st = 256; st > 0; st >>= 1) {
        if (tid < st) red[tid] = fmaxf(red[tid], red[tid + st]);
        __syncthreads();
    }
    const float m = red[0]; __syncthreads();
    red[tid] = expf(v - m); __syncthreads();
    for (int st = 256; st > 0; st >>= 1) {
        if (tid < st) red[tid] += red[tid + st];
        __syncthreads();
    }
    if (tid == 0) cl[b] = m + logf(red[0]) - pos;
}

// ---------------- final combine ----------------
__global__ void final_kernel(const float* __restrict__ ce, const float* __restrict__ m,
                             const float* __restrict__ cl, float* __restrict__ out)
{
    int tid = threadIdx.x;
    float v = ce[tid] * (1.0f / B_) + m[tid] + (ALPHA_ / B_) * cl[tid];
    __shared__ float red[512];
    red[tid] = v; __syncthreads();
    for (int st = 256; st > 0; st >>= 1) {
        if (tid < st) red[tid] += red[tid + st];
        __syncthreads();
    }
    if (tid == 0) out[0] = red[0];
}

// ---------------- host launcher (3-stream fork/join, graph-capturable) ----------------
extern "C" void kernel_launch(void* const* d_in, const int* in_sizes, int n_in,
                              void* d_out, int out_size)
{
    const float* bert    = (const float*)d_in[0];
    const float* rdesc   = (const float*)d_in[1];
    const float* dense_w = (const float*)d_in[2];
    const float* dense_b = (const float*)d_in[3];
    const float* cls_w   = (const float*)d_in[4];
    const float* cls_b   = (const float*)d_in[5];
    const float* fc_w    = (const float*)d_in[6];
    const float* fc_b    = (const float*)d_in[7];
    const int*   eidx    = (const int*)d_in[8];
    const int*   lab     = (const int*)d_in[9];
    float* out = (float*)d_out;

    __nv_bfloat16 *RHb,*TOKSb,*Wd,*Wp,*rdescb,*relb,*Db;
    float *biasP,*P1,*P2,*P3,*norms,*ce,*mm,*cl;
    cudaGetSymbolAddress((void**)&RHb,    g_RHb);
    cudaGetSymbolAddress((void**)&TOKSb,  g_TOKSb);
    cudaGetSymbolAddress((void**)&Wd,     g_Wd);
    cudaGetSymbolAddress((void**)&Wp,     g_Wp);
    cudaGetSymbolAddress((void**)&rdescb, g_rdescb);
    cudaGetSymbolAddress((void**)&relb,   g_relb);
    cudaGetSymbolAddress((void**)&Db,     g_Db);
    cudaGetSymbolAddress((void**)&biasP,  g_biasP);
    cudaGetSymbolAddress((void**)&P1,     g_P1);
    cudaGetSymbolAddress((void**)&P2,     g_P2);
    cudaGetSymbolAddress((void**)&P3,     g_P3);
    cudaGetSymbolAddress((void**)&norms,  g_norms);
    cudaGetSymbolAddress((void**)&ce,     g_ce);
    cudaGetSymbolAddress((void**)&mm,     g_m);
    cudaGetSymbolAddress((void**)&cl,     g_cl);

    static cudaStream_t s1 = nullptr, s2 = nullptr;
    static cudaEvent_t eFork, eG, ePrep, eM, eD, eZ;
    if (!s1) {
        cudaStreamCreateWithFlags(&s1, cudaStreamNonBlocking);
        cudaStreamCreateWithFlags(&s2, cudaStreamNonBlocking);
        cudaEventCreateWithFlags(&eFork, cudaEventDisableTiming);
        cudaEventCreateWithFlags(&eG,    cudaEventDisableTiming);
        cudaEventCreateWithFlags(&ePrep, cudaEventDisableTiming);
        cudaEventCreateWithFlags(&eM,    cudaEventDisableTiming);
        cudaEventCreateWithFlags(&eD,    cudaEventDisableTiming);
        cudaEventCreateWithFlags(&eZ,    cudaEventDisableTiming);
        cudaFuncSetAttribute(mma_nt<0>, cudaFuncAttributeMaxDynamicSharedMemorySize, DYN_SMEM_BYTES_);
        cudaFuncSetAttribute(mma_nt<1>, cudaFuncAttributeMaxDynamicSharedMemorySize, DYN_SMEM_BYTES_);
    }

    // fork s1, s2 from the captured (legacy) stream
    cudaEventRecord(eFork, 0);
    cudaStreamWaitEvent(s1, eFork, 0);
    cudaStreamWaitEvent(s2, eFork, 0);

    // s2: rdesc norm — depends on nothing but the input
    post_kernel<<<dim3(B_, 1), 256, 0, s2>>>(P1, biasP, rdesc, Db, lab, relb, norms, ce, 1, 0);

    // stream 0 (chain B): gather -> dense -> cos -> cl
    gather_kernel<<<B_, 192>>>(bert, eidx, RHb, TOKSb);
    cudaEventRecord(eG, 0);

    // stream 1 (chain A): prep -> (after gather) packed -> post0 -> C -> margin
    prep_kernel<<<PREP_BLOCKS_, dim3(32, 8), 0, s1>>>(dense_w, cls_w, fc_w, cls_b, fc_b,
                                                      rdesc, Wd, Wp, rdescb, biasP);
    cudaEventRecord(ePrep, s1);

    // dense on stream 0 needs Wd from prep
    cudaStreamWaitEvent(0, ePrep, 0);
    mma_nt<1><<<dim3(12, 16, 1), 256, DYN_SMEM_BYTES_>>>(TOKSb, Wd, nullptr, dense_b, Db,
        4*B_, H_, H_, H_, H_, H_, H_);
    cudaEventRecord(eD, 0);

    // s2: z-norms overlapped with the cos GEMM
    cudaStreamWaitEvent(s2, eD, 0);
    post_kernel<<<dim3(B_, 2), 256, 0, s2>>>(P1, biasP, rdesc, Db, lab, relb, norms, ce, 2, 0);
    cudaEventRecord(eZ, s2);

    // cos (NT): split-K 3 (8 tiles each) -> 96 CTAs, one wave
    mma_nt<0><<<dim3(8, 4, 3), 256, DYN_SMEM_BYTES_>>>(Db, Db + 2*H_, P3, nullptr, nullptr,
        B_, B_, 2*H_, 4*H_, 4*H_, B_, 512);
    cudaStreamWaitEvent(0, eZ, 0);
    cl_fused<<<B_, 512>>>(P3, norms, cl, 3);

    // chain A continues on s1 after gather (needs RHb)
    cudaStreamWaitEvent(s1, eG, 0);
    // packed: split-K 4 (9 tiles each, 36 total even) -> 112 CTAs
    mma_nt<0><<<dim3(7, 4, 4), 256, DYN_SMEM_BYTES_, s1>>>(RHb, Wp, P1, nullptr, nullptr,
        B_, NP2_, H3_, H3_, H3_, NP2_, 576);
    post_kernel<<<dim3(B_, 1), 256, 0, s1>>>(P1, biasP, rdesc, Db, lab, relb, norms, ce, 0, 4);
    // C: split-K 2 (3 tiles each) -> 64 CTAs
    mma_nt<0><<<dim3(8, 4, 2), 256, DYN_SMEM_BYTES_, s1>>>(relb, rdescb, P2, nullptr, nullptr,
        B_, B_, DS_, DS_, DS_, B_, 192);
    margin_fused<<<B_, 512, 0, s1>>>(P2, norms, lab, mm, 2);
    cudaEventRecord(eM, s1);

    // join and finish on stream 0
    cudaStreamWaitEvent(0, eM, 0);
    final_kernel<<<1, 512>>>(ce, mm, cl, out);
}